// round 14
// baseline (speedup 1.0000x reference)
#include <cuda_runtime.h>
#include <cuda_fp16.h>
#include <cstdint>
#include <math.h>

// ---------------------------------------------------------------------------
// Problem constants
// ---------------------------------------------------------------------------
#define BATCH 2
#define TSEQ  2048
#define DMODEL 1024
#define TE    64
#define CDIM  1088
#define NHEAD 16
#define HD    64
#define NTOK  (BATCH * TSEQ)  // 4096
#define EPSLN 1e-5f

// ---------------------------------------------------------------------------
// Scratch (static device arrays; no allocation anywhere)
// ---------------------------------------------------------------------------
__device__ float g_temb[BATCH * TE];
__device__ float g_h[NTOK * DMODEL];                 // proj out fp32
__device__ __half g_A[NTOK * CDIM];                  // LN out / attn y (single fp16)
__device__ __half g_Gh[NTOK * 4 * DMODEL];           // qkv hi, later gelu (single)
__device__ __half g_Gl[NTOK * 4 * DMODEL];           // qkv lo
__device__ __half g_Bh[4096 * 1088];                 // weight hi (transposed)
__device__ __half g_Bl[4096 * 1088];                 // weight lo

__device__ __forceinline__ float gelu_exact(float x) {
    return 0.5f * x * (1.0f + erff(x * 0.70710678118654752440f));
}
__device__ __forceinline__ void split_h16(float v, __half& h, __half& l) {
    h = __float2half_rn(v);
    l = __float2half_rn(v - __half2float(h));
}
__device__ __forceinline__ uint32_t pack_h16(__half a, __half b) {
    __half2 p; p.x = a; p.y = b;
    return *(uint32_t*)&p;
}

// ---------------------------------------------------------------------------
// PTX helpers (baseline PTX only: cp.async, ldmatrix, mma.sync)
// ---------------------------------------------------------------------------
__device__ __forceinline__ uint32_t smem_u32(const void* p) {
    uint32_t a;
    asm("{ .reg .u64 t; cvta.to.shared.u64 t, %1; cvt.u32.u64 %0, t; }" : "=r"(a) : "l"(p));
    return a;
}
#define SW128(off) ((off) ^ (((off) >> 3) & 0x70))

__device__ __forceinline__ void cp16(uint32_t dst, const void* src) {
    asm volatile("cp.async.cg.shared.global [%0], [%1], 16;" :: "r"(dst), "l"(src) : "memory");
}
__device__ __forceinline__ void cp_commit() { asm volatile("cp.async.commit_group;" ::: "memory"); }
__device__ __forceinline__ void cp_wait1() { asm volatile("cp.async.wait_group 1;" ::: "memory"); }
__device__ __forceinline__ void cp_wait0() { asm volatile("cp.async.wait_group 0;" ::: "memory"); }

__device__ __forceinline__ void ldsm_x4(uint32_t (&r)[4], uint32_t addr) {
    asm volatile("ldmatrix.sync.aligned.m8n8.x4.shared.b16 {%0,%1,%2,%3}, [%4];"
        : "=r"(r[0]), "=r"(r[1]), "=r"(r[2]), "=r"(r[3]) : "r"(addr));
}
__device__ __forceinline__ void ldsm_x4_t(uint32_t (&r)[4], uint32_t addr) {
    asm volatile("ldmatrix.sync.aligned.m8n8.x4.trans.shared.b16 {%0,%1,%2,%3}, [%4];"
        : "=r"(r[0]), "=r"(r[1]), "=r"(r[2]), "=r"(r[3]) : "r"(addr));
}
__device__ __forceinline__ void mma16816(float (&d)[4], const uint32_t (&a)[4],
                                         uint32_t b0, uint32_t b1) {
    asm volatile("mma.sync.aligned.m16n8k16.row.col.f32.f16.f16.f32 "
        "{%0,%1,%2,%3}, {%4,%5,%6,%7}, {%8,%9}, {%0,%1,%2,%3};"
        : "+f"(d[0]), "+f"(d[1]), "+f"(d[2]), "+f"(d[3])
        : "r"(a[0]), "r"(a[1]), "r"(a[2]), "r"(a[3]), "r"(b0), "r"(b1));
}

// ---------------------------------------------------------------------------
// Time MLP
// ---------------------------------------------------------------------------
__global__ void time_mlp_kernel(const float* __restrict__ t,
                                const float* __restrict__ w1, const float* __restrict__ b1,
                                const float* __restrict__ w2, const float* __restrict__ b2) {
    int b = blockIdx.x;
    int e = threadIdx.x;
    __shared__ float h1[TE];
    h1[e] = gelu_exact(t[b] * w1[e] + b1[e]);
    __syncthreads();
    float acc = b2[e];
    #pragma unroll 8
    for (int i = 0; i < TE; i++) acc += h1[i] * w2[i * TE + e];
    g_temb[b * TE + e] = acc;
}

// ---------------------------------------------------------------------------
// LayerNorm over concat([x(1024), t_emb(64)]) -> single fp16 [NTOK, 1088]
// ---------------------------------------------------------------------------
__global__ void ln_concat_kernel(const float* __restrict__ x,
                                 const float* __restrict__ w,
                                 const float* __restrict__ bias,
                                 __half* __restrict__ oh) {
    const int token = blockIdx.x;
    const int b = token >> 11;
    const int tid = threadIdx.x;

    __shared__ float xs[CDIM];
    __shared__ float red[16];

    float sum = 0.f, sumsq = 0.f;
    for (int c = tid; c < CDIM; c += 256) {
        float v = (c < DMODEL) ? x[(size_t)token * DMODEL + c] : g_temb[b * TE + (c - DMODEL)];
        xs[c] = v;
        sum += v;
        sumsq += v * v;
    }
    #pragma unroll
    for (int o = 16; o > 0; o >>= 1) {
        sum   += __shfl_xor_sync(0xffffffffu, sum, o);
        sumsq += __shfl_xor_sync(0xffffffffu, sumsq, o);
    }
    int warp = tid >> 5, lane = tid & 31;
    if (lane == 0) { red[warp] = sum; red[warp + 8] = sumsq; }
    __syncthreads();
    if (tid == 0) {
        float s = 0.f, sq = 0.f;
        #pragma unroll
        for (int i = 0; i < 8; i++) { s += red[i]; sq += red[i + 8]; }
        float mu = s * (1.0f / CDIM);
        float var = sq * (1.0f / CDIM) - mu * mu;
        red[0] = mu;
        red[1] = rsqrtf(var + EPSLN);
    }
    __syncthreads();
    float mu = red[0], rs = red[1];
    for (int c = tid; c < CDIM; c += 256) {
        float v = (xs[c] - mu) * rs * w[c] + bias[c];
        oh[(size_t)token * CDIM + c] = __float2half_rn(v);
    }
}

// ---------------------------------------------------------------------------
// Weight convert + transpose: w[K,N] fp32 -> oh/ol[N,K] fp16 hi/lo
// ---------------------------------------------------------------------------
__global__ void wconv_kernel(const float* __restrict__ w,
                             __half* __restrict__ oh, __half* __restrict__ ol,
                             int K, int N) {
    __shared__ float tile[32][33];
    int nb = blockIdx.x * 32, kb = blockIdx.y * 32;
    int tx = threadIdx.x, ty = threadIdx.y;
    #pragma unroll
    for (int i = 0; i < 32; i += 8)
        tile[ty + i][tx] = w[(size_t)(kb + ty + i) * N + nb + tx];
    __syncthreads();
    #pragma unroll
    for (int i = 0; i < 32; i += 8) {
        float v = tile[tx][ty + i];
        __half h, l;
        split_h16(v, h, l);
        oh[(size_t)(nb + ty + i) * K + kb + tx] = h;
        ol[(size_t)(nb + ty + i) * K + kb + tx] = l;
    }
}

// ---------------------------------------------------------------------------
// mma.sync fp16x2 GEMM: C[M,N] = A[M,K] @ (Bh+Bl)^T  (B stored [N,K]).
// CTA 256x128, BK=64 fp16, 256 threads (8 warps 4Mx2N), warp tile m64xn64.
// 2-stage cp.async. B fragments REUSED in place (load Bh, pass, load Bl,
// pass) to keep live regs under the 255 ceiling -> no spills.
// ---------------------------------------------------------------------------
#define STG 65536
#define SM_TOT (2 * STG)

template <bool GELU, bool OUTF32, bool OUTHILO>
__global__ __launch_bounds__(256, 1)
void mma_gemm(const __half* __restrict__ A, int lda,
              const __half* __restrict__ Bh, const __half* __restrict__ Bl,
              const float* __restrict__ bias,
              float* __restrict__ Cf, __half* __restrict__ Ch, __half* __restrict__ Cl,
              int ldc, int K) {
    extern __shared__ char smem[];
    const uint32_t sb = smem_u32(smem);
    const int tid = threadIdx.x;
    const int lane = tid & 31;
    const int wid = tid >> 5;
    const int wm = wid & 3;        // rows wm*64..+63
    const int wn = wid >> 2;       // cols wn*64..+63
    const int bm = blockIdx.y * 256;
    const int bn = blockIdx.x * 128;
    const int nch = K >> 6;

    float acc[4][8][4];
    #pragma unroll
    for (int i = 0; i < 4; i++)
        #pragma unroll
        for (int j = 0; j < 8; j++)
            #pragma unroll
            for (int q = 0; q < 4; q++) acc[i][j][q] = 0.f;

    auto load_stage = [&](int c, int s) {
        const int k0 = c * 64;
        const uint32_t base = sb + s * STG;
        // A: 256 rows x 8 x 16B
        #pragma unroll
        for (int i = 0; i < 8; i++) {
            int id = tid + i * 256;          // 0..2047
            int row = id >> 3;
            int c16 = id & 7;
            uint32_t off = SW128(row * 128 + c16 * 16);
            cp16(base + off, A + (size_t)(bm + row) * lda + k0 + c16 * 8);
        }
        // B hi + lo: 128 rows x 8 x 16B each
        #pragma unroll
        for (int i = 0; i < 4; i++) {
            int id = tid + i * 256;          // 0..1023
            int row = id >> 3;
            int c16 = id & 7;
            uint32_t off = SW128(row * 128 + c16 * 16);
            const size_t gb = (size_t)(bn + row) * K + k0 + c16 * 8;
            cp16(base + 32768 + off, Bh + gb);
            cp16(base + 49152 + off, Bl + gb);
        }
        cp_commit();
    };

    load_stage(0, 0);

    const int a_row = (lane & 15);
    const int a_col16 = (lane >> 4) << 4;
    const int b_grp = lane >> 3;
    const int b_row = ((b_grp >> 1) << 3) + (lane & 7);
    const int b_col16 = (b_grp & 1) << 4;

    for (int c = 0; c < nch; c++) {
        const int st = c & 1;
        if (c + 1 < nch) { load_stage(c + 1, st ^ 1); cp_wait1(); }
        else             { cp_wait0(); }
        __syncthreads();

        const uint32_t a_b  = sb + st * STG;
        const uint32_t bh_b = a_b + 32768;
        const uint32_t bl_b = a_b + 49152;

        #pragma unroll
        for (int ks = 0; ks < 4; ks++) {
            const int kb = ks * 32;
            uint32_t fa[4][4];
            #pragma unroll
            for (int mt = 0; mt < 4; mt++) {
                int row = wm * 64 + mt * 16 + a_row;
                uint32_t off = SW128(row * 128 + kb + a_col16);
                ldsm_x4(fa[mt], a_b + off);
            }
            uint32_t fb[4][4];   // reused for Bh then Bl
            // pass 1: A * Bh
            #pragma unroll
            for (int nb = 0; nb < 4; nb++) {
                int row = wn * 64 + nb * 16 + b_row;
                uint32_t off = SW128(row * 128 + kb + b_col16);
                ldsm_x4(fb[nb], bh_b + off);
            }
            #pragma unroll
            for (int mt = 0; mt < 4; mt++)
                #pragma unroll
                for (int nt = 0; nt < 8; nt++)
                    mma16816(acc[mt][nt], fa[mt],
                             fb[nt >> 1][(nt & 1) * 2], fb[nt >> 1][(nt & 1) * 2 + 1]);
            // pass 2: A * Bl (reload fb in place)
            #pragma unroll
            for (int nb = 0; nb < 4; nb++) {
                int row = wn * 64 + nb * 16 + b_row;
                uint32_t off = SW128(row * 128 + kb + b_col16);
                ldsm_x4(fb[nb], bl_b + off);
            }
            #pragma unroll
            for (int mt = 0; mt < 4; mt++)
                #pragma unroll
                for (int nt = 0; nt < 8; nt++)
                    mma16816(acc[mt][nt], fa[mt],
                             fb[nt >> 1][(nt & 1) * 2], fb[nt >> 1][(nt & 1) * 2 + 1]);
        }
        __syncthreads();
    }

    #pragma unroll
    for (int mt = 0; mt < 4; mt++) {
        #pragma unroll
        for (int nt = 0; nt < 8; nt++) {
            int r0  = bm + wm * 64 + mt * 16 + (lane >> 2);
            int col = bn + wn * 64 + nt * 8 + ((lane & 3) << 1);
            float bi0 = bias[col], bi1 = bias[col + 1];
            #pragma unroll
            for (int half_ = 0; half_ < 2; half_++) {
                size_t row = r0 + half_ * 8;
                float v0 = acc[mt][nt][half_ * 2 + 0] + bi0;
                float v1 = acc[mt][nt][half_ * 2 + 1] + bi1;
                if (GELU) { v0 = gelu_exact(v0); v1 = gelu_exact(v1); }
                if (OUTF32) {
                    float2 o2 = make_float2(v0, v1);
                    *(float2*)&Cf[row * ldc + col] = o2;
                } else if (OUTHILO) {
                    __half h0, l0, h1, l1;
                    split_h16(v0, h0, l0);
                    split_h16(v1, h1, l1);
                    *(uint32_t*)&Ch[row * ldc + col] = pack_h16(h0, h1);
                    *(uint32_t*)&Cl[row * ldc + col] = pack_h16(l0, l1);
                } else {
                    *(uint32_t*)&Ch[row * ldc + col] =
                        pack_h16(__float2half_rn(v0), __float2half_rn(v1));
                }
            }
        }
    }
}

// ---------------------------------------------------------------------------
// Tensor-core causal flash attention.
// QK^T: 3-pass fp16 (QhKh + QhKl + QlKh); PV: 2-pass fp16 (P*(Vh+Vl)).
// grid (32, 16, 2) qt reversed; 128 threads = 4 warps, warp = m16 x n64.
// ---------------------------------------------------------------------------
#define ATT_SMEM (16384 + 2 * 32768)

__global__ __launch_bounds__(128, 1)
void attn_mma_kernel(const __half* __restrict__ QKVh,
                     const __half* __restrict__ QKVl,
                     __half* __restrict__ y) {
    extern __shared__ char smem[];
    const uint32_t sb = smem_u32(smem);
    const int qt = (int)gridDim.x - 1 - (int)blockIdx.x;
    const int h = blockIdx.y, b = blockIdx.z;
    const int tid = threadIdx.x, lane = tid & 31, wm = tid >> 5;
    const int base = b * TSEQ;
    const size_t qstride = 3 * DMODEL;

    const uint32_t sQh = sb, sQl = sb + 8192;

    #pragma unroll
    for (int i = 0; i < 4; i++) {
        int id = tid + i * 128;
        int row = id >> 3, c = id & 7;
        uint32_t off = SW128(row * 128 + c * 16);
        size_t g = (size_t)(base + qt * 64 + row) * qstride + h * HD + c * 8;
        cp16(sQh + off, QKVh + g);
        cp16(sQl + off, QKVl + g);
    }
    auto load_kv = [&](int kt, int s) {
        uint32_t kb_ = sb + 16384 + s * 32768;
        #pragma unroll
        for (int i = 0; i < 4; i++) {
            int id = tid + i * 128;
            int row = id >> 3, c = id & 7;
            uint32_t off = SW128(row * 128 + c * 16);
            size_t gk = (size_t)(base + kt * 64 + row) * qstride + DMODEL + h * HD + c * 8;
            size_t gv = gk + DMODEL;
            cp16(kb_ + off,          QKVh + gk);
            cp16(kb_ + 8192 + off,   QKVl + gk);
            cp16(kb_ + 16384 + off,  QKVh + gv);
            cp16(kb_ + 24576 + off,  QKVl + gv);
        }
    };
    load_kv(0, 0);
    cp_commit();

    float oacc[8][4];
    #pragma unroll
    for (int i = 0; i < 8; i++)
        #pragma unroll
        for (int j = 0; j < 4; j++) oacc[i][j] = 0.f;
    float m0 = -INFINITY, m1 = -INFINITY, l0 = 0.f, l1 = 0.f;

    for (int kt = 0; kt <= qt; kt++) {
        const int st = kt & 1;
        if (kt < qt) { load_kv(kt + 1, st ^ 1); cp_commit(); cp_wait1(); }
        else         { cp_wait0(); }
        __syncthreads();

        const uint32_t sKh = sb + 16384 + st * 32768;
        const uint32_t sKl = sKh + 8192;
        const uint32_t sVh = sKh + 16384;
        const uint32_t sVl = sKh + 24576;

        float sacc[8][4];
        #pragma unroll
        for (int i = 0; i < 8; i++)
            #pragma unroll
            for (int j = 0; j < 4; j++) sacc[i][j] = 0.f;

        #pragma unroll
        for (int ks = 0; ks < 4; ks++) {
            uint32_t qh[4], ql[4];
            {
                int r = wm * 16 + (lane & 15);
                int byt = ks * 32 + ((lane >> 4) << 4);
                uint32_t off = SW128(r * 128 + byt);
                ldsm_x4(qh, sQh + off);
                ldsm_x4(ql, sQl + off);
            }
            #pragma unroll
            for (int nb2 = 0; nb2 < 4; nb2++) {
                uint32_t kh[4], kl[4];
                int grp = lane >> 3;
                int r = nb2 * 16 + ((grp >> 1) << 3) + (lane & 7);
                int byt = ks * 32 + ((grp & 1) << 4);
                uint32_t off = SW128(r * 128 + byt);
                ldsm_x4(kh, sKh + off);
                ldsm_x4(kl, sKl + off);
                mma16816(sacc[2 * nb2],     qh, kh[0], kh[1]);
                mma16816(sacc[2 * nb2],     qh, kl[0], kl[1]);
                mma16816(sacc[2 * nb2],     ql, kh[0], kh[1]);
                mma16816(sacc[2 * nb2 + 1], qh, kh[2], kh[3]);
                mma16816(sacc[2 * nb2 + 1], qh, kl[2], kl[3]);
                mma16816(sacc[2 * nb2 + 1], ql, kh[2], kh[3]);
            }
        }

        const bool diag = (kt == qt);
        const int lr0 = wm * 16 + (lane >> 2);
        #pragma unroll
        for (int nt = 0; nt < 8; nt++) {
            int c0 = nt * 8 + 2 * (lane & 3);
            #pragma unroll
            for (int j = 0; j < 4; j++) {
                float v = sacc[nt][j] * 0.125f;
                if (diag && (c0 + (j & 1)) > (lr0 + (j >> 1) * 8)) v = -1e30f;
                sacc[nt][j] = v;
            }
        }

        float r0m = -1e30f, r1m = -1e30f;
        #pragma unroll
        for (int nt = 0; nt < 8; nt++) {
            r0m = fmaxf(r0m, fmaxf(sacc[nt][0], sacc[nt][1]));
            r1m = fmaxf(r1m, fmaxf(sacc[nt][2], sacc[nt][3]));
        }
        r0m = fmaxf(r0m, __shfl_xor_sync(0xffffffffu, r0m, 1));
        r0m = fmaxf(r0m, __shfl_xor_sync(0xffffffffu, r0m, 2));
        r1m = fmaxf(r1m, __shfl_xor_sync(0xffffffffu, r1m, 1));
        r1m = fmaxf(r1m, __shfl_xor_sync(0xffffffffu, r1m, 2));
        float m0n = fmaxf(m0, r0m), m1n = fmaxf(m1, r1m);
        float cr0 = __expf(m0 - m0n), cr1 = __expf(m1 - m1n);
        m0 = m0n; m1 = m1n;
        l0 *= cr0; l1 *= cr1;
        #pragma unroll
        for (int nt = 0; nt < 8; nt++) {
            oacc[nt][0] *= cr0; oacc[nt][1] *= cr0;
            oacc[nt][2] *= cr1; oacc[nt][3] *= cr1;
        }
        float ps0 = 0.f, ps1 = 0.f;
        #pragma unroll
        for (int nt = 0; nt < 8; nt++) {
            float p0 = __expf(sacc[nt][0] - m0);
            float p1 = __expf(sacc[nt][1] - m0);
            float p2 = __expf(sacc[nt][2] - m1);
            float p3 = __expf(sacc[nt][3] - m1);
            ps0 += p0 + p1; ps1 += p2 + p3;
            sacc[nt][0] = p0; sacc[nt][1] = p1; sacc[nt][2] = p2; sacc[nt][3] = p3;
        }
        l0 += ps0; l1 += ps1;

        // --- O += P (Vh + Vl), P in single fp16 ---
        #pragma unroll
        for (int s = 0; s < 4; s++) {
            uint32_t aP[4];
            #pragma unroll
            for (int half_ = 0; half_ < 2; half_++) {
                int blk = 2 * s + half_;
                aP[2 * half_ + 0] = pack_h16(__float2half_rn(sacc[blk][0]),
                                             __float2half_rn(sacc[blk][1]));
                aP[2 * half_ + 1] = pack_h16(__float2half_rn(sacc[blk][2]),
                                             __float2half_rn(sacc[blk][3]));
            }
            #pragma unroll
            for (int dd = 0; dd < 4; dd++) {
                uint32_t vh[4], vl[4];
                int grp = lane >> 3;
                int key = s * 16 + (grp & 1) * 8 + (lane & 7);
                int byt = dd * 32 + ((grp >> 1) << 4);
                uint32_t off = SW128(key * 128 + byt);
                ldsm_x4_t(vh, sVh + off);
                ldsm_x4_t(vl, sVl + off);
                mma16816(oacc[2 * dd],     aP, vh[0], vh[1]);
                mma16816(oacc[2 * dd],     aP, vl[0], vl[1]);
                mma16816(oacc[2 * dd + 1], aP, vh[2], vh[3]);
                mma16816(oacc[2 * dd + 1], aP, vl[2], vl[3]);
            }
        }
        __syncthreads();
    }

    l0 += __shfl_xor_sync(0xffffffffu, l0, 1);
    l0 += __shfl_xor_sync(0xffffffffu, l0, 2);
    l1 += __shfl_xor_sync(0xffffffffu, l1, 1);
    l1 += __shfl_xor_sync(0xffffffffu, l1, 2);
    float inv0 = 1.0f / l0, inv1 = 1.0f / l1;

    const size_t gr0 = (size_t)(base + qt * 64 + wm * 16 + (lane >> 2));
    const int colb = h * HD + 2 * (lane & 3);
    #pragma unroll
    for (int nt = 0; nt < 8; nt++) {
        int col = colb + nt * 8;
        *(uint32_t*)&y[gr0 * DMODEL + col] =
            pack_h16(__float2half_rn(oacc[nt][0] * inv0),
                     __float2half_rn(oacc[nt][1] * inv0));
        *(uint32_t*)&y[(gr0 + 8) * DMODEL + col] =
            pack_h16(__float2half_rn(oacc[nt][2] * inv1),
                     __float2half_rn(oacc[nt][3] * inv1));
    }
}

// ---------------------------------------------------------------------------
// Launch
// ---------------------------------------------------------------------------
extern "C" void kernel_launch(void* const* d_in, const int* in_sizes, int n_in,
                              void* d_out, int out_size) {
    const float* z      = (const float*)d_in[0];
    const float* t      = (const float*)d_in[1];
    const float* w_t1   = (const float*)d_in[2];
    const float* b_t1   = (const float*)d_in[3];
    const float* w_t2   = (const float*)d_in[4];
    const float* b_t2   = (const float*)d_in[5];
    const float* ln_a_w = (const float*)d_in[6];
    const float* ln_a_b = (const float*)d_in[7];
    const float* w_attn = (const float*)d_in[8];
    const float* b_attn = (const float*)d_in[9];
    const float* w_proj = (const float*)d_in[10];
    const float* b_proj = (const float*)d_in[11];
    const float* ln_m_w = (const float*)d_in[12];
    const float* ln_m_b = (const float*)d_in[13];
    const float* w_fc   = (const float*)d_in[14];
    const float* b_fc   = (const float*)d_in[15];
    const float* w_fc2  = (const float*)d_in[16];
    const float* b_fc2  = (const float*)d_in[17];
    float* out = (float*)d_out;
    (void)n_in; (void)in_sizes; (void)out_size;

    float* gh;
    __half *gA, *gGh, *gGl, *gBh, *gBl;
    cudaGetSymbolAddress((void**)&gh,  g_h);
    cudaGetSymbolAddress((void**)&gA,  g_A);
    cudaGetSymbolAddress((void**)&gGh, g_Gh);
    cudaGetSymbolAddress((void**)&gGl, g_Gl);
    cudaGetSymbolAddress((void**)&gBh, g_Bh);
    cudaGetSymbolAddress((void**)&gBl, g_Bl);

    cudaFuncSetAttribute(mma_gemm<false, true, false>,
                         cudaFuncAttributeMaxDynamicSharedMemorySize, SM_TOT);
    cudaFuncSetAttribute(mma_gemm<true, false, false>,
                         cudaFuncAttributeMaxDynamicSharedMemorySize, SM_TOT);
    cudaFuncSetAttribute(mma_gemm<false, false, true>,
                         cudaFuncAttributeMaxDynamicSharedMemorySize, SM_TOT);
    cudaFuncSetAttribute(attn_mma_kernel,
                         cudaFuncAttributeMaxDynamicSharedMemorySize, ATT_SMEM);

    // 1. time embedding
    time_mlp_kernel<<<BATCH, TE>>>(t, w_t1, b_t1, w_t2, b_t2);

    // 2. LN(concat(z, temb)) -> fp16 [4096,1088]
    ln_concat_kernel<<<NTOK, 256>>>(z, ln_a_w, ln_a_b, gA);

    // 3. qkv GEMM -> fp16 hi/lo [4096,3072] in g_G
    wconv_kernel<<<dim3(3 * DMODEL / 32, CDIM / 32), dim3(32, 8)>>>(w_attn, gBh, gBl, CDIM, 3 * DMODEL);
    mma_gemm<false, false, true><<<dim3(3 * DMODEL / 128, NTOK / 256), 256, SM_TOT>>>(
        gA, CDIM, gBh, gBl, b_attn, nullptr, gGh, gGl, 3 * DMODEL, CDIM);

    // 4. tensor-core attention -> y fp16 in g_A (stride 1024)
    attn_mma_kernel<<<dim3(TSEQ / 64, NHEAD, BATCH), 128, ATT_SMEM>>>(gGh, gGl, gA);

    // 5. proj GEMM -> fp32 g_h
    wconv_kernel<<<dim3(DMODEL / 32, DMODEL / 32), dim3(32, 8)>>>(w_proj, gBh, gBl, DMODEL, DMODEL);
    mma_gemm<false, true, false><<<dim3(DMODEL / 128, NTOK / 256), 256, SM_TOT>>>(
        gA, DMODEL, gBh, gBl, b_proj, gh, nullptr, nullptr, DMODEL, DMODEL);

    // 6. LN(concat(h, temb)) -> fp16 [4096,1088]
    ln_concat_kernel<<<NTOK, 256>>>(gh, ln_m_w, ln_m_b, gA);

    // 7. fc GEMM + GELU -> single fp16 [4096,4096] in g_Gh
    wconv_kernel<<<dim3(4 * DMODEL / 32, CDIM / 32), dim3(32, 8)>>>(w_fc, gBh, gBl, CDIM, 4 * DMODEL);
    mma_gemm<true, false, false><<<dim3(4 * DMODEL / 128, NTOK / 256), 256, SM_TOT>>>(
        gA, CDIM, gBh, gBl, b_fc, nullptr, gGh, nullptr, 4 * DMODEL, CDIM);

    // 8. fc2 GEMM -> fp32 out
    wconv_kernel<<<dim3(DMODEL / 32, 4 * DMODEL / 32), dim3(32, 8)>>>(w_fc2, gBh, gBl, 4 * DMODEL, DMODEL);
    mma_gemm<false, true, false><<<dim3(DMODEL / 128, NTOK / 256), 256, SM_TOT>>>(
        gGh, 4 * DMODEL, gBh, gBl, b_fc2, out, nullptr, nullptr, DMODEL, 4 * DMODEL);
}

// round 15
// speedup vs baseline: 1.0023x; 1.0023x over previous
#include <cuda_runtime.h>
#include <cuda_fp16.h>
#include <cstdint>
#include <math.h>

// ---------------------------------------------------------------------------
// Problem constants
// ---------------------------------------------------------------------------
#define BATCH 2
#define TSEQ  2048
#define DMODEL 1024
#define TE    64
#define CDIM  1088
#define NHEAD 16
#define HD    64
#define NTOK  (BATCH * TSEQ)  // 4096
#define EPSLN 1e-5f

// ---------------------------------------------------------------------------
// Scratch (static device arrays; no allocation anywhere)
// ---------------------------------------------------------------------------
__device__ float g_temb[BATCH * TE];
__device__ float g_h[NTOK * DMODEL];                 // proj out fp32
__device__ __half g_A[NTOK * CDIM];                  // LN out / attn y (single fp16)
__device__ __half g_Gh[NTOK * 4 * DMODEL];           // qkv hi, later gelu (single)
__device__ __half g_Gl[NTOK * 4 * DMODEL];           // qkv lo
__device__ __half g_Bh[4096 * 1088];                 // weight hi (transposed)
__device__ __half g_Bl[4096 * 1088];                 // weight lo

__device__ __forceinline__ float gelu_exact(float x) {
    return 0.5f * x * (1.0f + erff(x * 0.70710678118654752440f));
}
__device__ __forceinline__ void split_h16(float v, __half& h, __half& l) {
    h = __float2half_rn(v);
    l = __float2half_rn(v - __half2float(h));
}
__device__ __forceinline__ uint32_t pack_h16(__half a, __half b) {
    __half2 p; p.x = a; p.y = b;
    return *(uint32_t*)&p;
}

// ---------------------------------------------------------------------------
// PTX helpers (baseline PTX only: cp.async, ldmatrix, mma.sync)
// ---------------------------------------------------------------------------
__device__ __forceinline__ uint32_t smem_u32(const void* p) {
    uint32_t a;
    asm("{ .reg .u64 t; cvta.to.shared.u64 t, %1; cvt.u32.u64 %0, t; }" : "=r"(a) : "l"(p));
    return a;
}
#define SW128(off) ((off) ^ (((off) >> 3) & 0x70))

__device__ __forceinline__ void cp16(uint32_t dst, const void* src) {
    asm volatile("cp.async.cg.shared.global [%0], [%1], 16;" :: "r"(dst), "l"(src) : "memory");
}
__device__ __forceinline__ void cp_commit() { asm volatile("cp.async.commit_group;" ::: "memory"); }
__device__ __forceinline__ void cp_wait1() { asm volatile("cp.async.wait_group 1;" ::: "memory"); }
__device__ __forceinline__ void cp_wait0() { asm volatile("cp.async.wait_group 0;" ::: "memory"); }

__device__ __forceinline__ void ldsm_x4(uint32_t (&r)[4], uint32_t addr) {
    asm volatile("ldmatrix.sync.aligned.m8n8.x4.shared.b16 {%0,%1,%2,%3}, [%4];"
        : "=r"(r[0]), "=r"(r[1]), "=r"(r[2]), "=r"(r[3]) : "r"(addr));
}
__device__ __forceinline__ void ldsm_x4_t(uint32_t (&r)[4], uint32_t addr) {
    asm volatile("ldmatrix.sync.aligned.m8n8.x4.trans.shared.b16 {%0,%1,%2,%3}, [%4];"
        : "=r"(r[0]), "=r"(r[1]), "=r"(r[2]), "=r"(r[3]) : "r"(addr));
}
__device__ __forceinline__ void mma16816(float (&d)[4], const uint32_t (&a)[4],
                                         uint32_t b0, uint32_t b1) {
    asm volatile("mma.sync.aligned.m16n8k16.row.col.f32.f16.f16.f32 "
        "{%0,%1,%2,%3}, {%4,%5,%6,%7}, {%8,%9}, {%0,%1,%2,%3};"
        : "+f"(d[0]), "+f"(d[1]), "+f"(d[2]), "+f"(d[3])
        : "r"(a[0]), "r"(a[1]), "r"(a[2]), "r"(a[3]), "r"(b0), "r"(b1));
}

// ---------------------------------------------------------------------------
// Time MLP
// ---------------------------------------------------------------------------
__global__ void time_mlp_kernel(const float* __restrict__ t,
                                const float* __restrict__ w1, const float* __restrict__ b1,
                                const float* __restrict__ w2, const float* __restrict__ b2) {
    int b = blockIdx.x;
    int e = threadIdx.x;
    __shared__ float h1[TE];
    h1[e] = gelu_exact(t[b] * w1[e] + b1[e]);
    __syncthreads();
    float acc = b2[e];
    #pragma unroll 8
    for (int i = 0; i < TE; i++) acc += h1[i] * w2[i * TE + e];
    g_temb[b * TE + e] = acc;
}

// ---------------------------------------------------------------------------
// LayerNorm over concat([x(1024), t_emb(64)]) -> single fp16 [NTOK, 1088]
// ---------------------------------------------------------------------------
__global__ void ln_concat_kernel(const float* __restrict__ x,
                                 const float* __restrict__ w,
                                 const float* __restrict__ bias,
                                 __half* __restrict__ oh) {
    const int token = blockIdx.x;
    const int b = token >> 11;
    const int tid = threadIdx.x;

    __shared__ float xs[CDIM];
    __shared__ float red[16];

    float sum = 0.f, sumsq = 0.f;
    for (int c = tid; c < CDIM; c += 256) {
        float v = (c < DMODEL) ? x[(size_t)token * DMODEL + c] : g_temb[b * TE + (c - DMODEL)];
        xs[c] = v;
        sum += v;
        sumsq += v * v;
    }
    #pragma unroll
    for (int o = 16; o > 0; o >>= 1) {
        sum   += __shfl_xor_sync(0xffffffffu, sum, o);
        sumsq += __shfl_xor_sync(0xffffffffu, sumsq, o);
    }
    int warp = tid >> 5, lane = tid & 31;
    if (lane == 0) { red[warp] = sum; red[warp + 8] = sumsq; }
    __syncthreads();
    if (tid == 0) {
        float s = 0.f, sq = 0.f;
        #pragma unroll
        for (int i = 0; i < 8; i++) { s += red[i]; sq += red[i + 8]; }
        float mu = s * (1.0f / CDIM);
        float var = sq * (1.0f / CDIM) - mu * mu;
        red[0] = mu;
        red[1] = rsqrtf(var + EPSLN);
    }
    __syncthreads();
    float mu = red[0], rs = red[1];
    for (int c = tid; c < CDIM; c += 256) {
        float v = (xs[c] - mu) * rs * w[c] + bias[c];
        oh[(size_t)token * CDIM + c] = __float2half_rn(v);
    }
}

// ---------------------------------------------------------------------------
// Weight convert + transpose: w[K,N] fp32 -> oh/ol[N,K] fp16 hi/lo
// ---------------------------------------------------------------------------
__global__ void wconv_kernel(const float* __restrict__ w,
                             __half* __restrict__ oh, __half* __restrict__ ol,
                             int K, int N) {
    __shared__ float tile[32][33];
    int nb = blockIdx.x * 32, kb = blockIdx.y * 32;
    int tx = threadIdx.x, ty = threadIdx.y;
    #pragma unroll
    for (int i = 0; i < 32; i += 8)
        tile[ty + i][tx] = w[(size_t)(kb + ty + i) * N + nb + tx];
    __syncthreads();
    #pragma unroll
    for (int i = 0; i < 32; i += 8) {
        float v = tile[tx][ty + i];
        __half h, l;
        split_h16(v, h, l);
        oh[(size_t)(nb + ty + i) * K + kb + tx] = h;
        ol[(size_t)(nb + ty + i) * K + kb + tx] = l;
    }
}

// ---------------------------------------------------------------------------
// mma.sync fp16x2 GEMM: C[M,N] = A[M,K] @ (Bh+Bl)^T  (B stored [N,K]).
// CTA 256x128, BK=64 fp16, 256 threads (8 warps 4Mx2N), warp tile m64xn64.
// 2-stage cp.async. B fragments STREAMED one ldsm.x4 at a time (4 live regs)
// so total live regs ~190 -> no spills (the R10/R14 builds spilled at 255).
// ---------------------------------------------------------------------------
#define STG 65536
#define SM_TOT (2 * STG)

template <bool GELU, bool OUTF32, bool OUTHILO>
__global__ __launch_bounds__(256, 1)
void mma_gemm(const __half* __restrict__ A, int lda,
              const __half* __restrict__ Bh, const __half* __restrict__ Bl,
              const float* __restrict__ bias,
              float* __restrict__ Cf, __half* __restrict__ Ch, __half* __restrict__ Cl,
              int ldc, int K) {
    extern __shared__ char smem[];
    const uint32_t sb = smem_u32(smem);
    const int tid = threadIdx.x;
    const int lane = tid & 31;
    const int wid = tid >> 5;
    const int wm = wid & 3;        // rows wm*64..+63
    const int wn = wid >> 2;       // cols wn*64..+63
    const int bm = blockIdx.y * 256;
    const int bn = blockIdx.x * 128;
    const int nch = K >> 6;

    float acc[4][8][4];
    #pragma unroll
    for (int i = 0; i < 4; i++)
        #pragma unroll
        for (int j = 0; j < 8; j++)
            #pragma unroll
            for (int q = 0; q < 4; q++) acc[i][j][q] = 0.f;

    auto load_stage = [&](int c, int s) {
        const int k0 = c * 64;
        const uint32_t base = sb + s * STG;
        // A: 256 rows x 8 x 16B
        #pragma unroll
        for (int i = 0; i < 8; i++) {
            int id = tid + i * 256;          // 0..2047
            int row = id >> 3;
            int c16 = id & 7;
            uint32_t off = SW128(row * 128 + c16 * 16);
            cp16(base + off, A + (size_t)(bm + row) * lda + k0 + c16 * 8);
        }
        // B hi + lo: 128 rows x 8 x 16B each
        #pragma unroll
        for (int i = 0; i < 4; i++) {
            int id = tid + i * 256;          // 0..1023
            int row = id >> 3;
            int c16 = id & 7;
            uint32_t off = SW128(row * 128 + c16 * 16);
            const size_t gb = (size_t)(bn + row) * K + k0 + c16 * 8;
            cp16(base + 32768 + off, Bh + gb);
            cp16(base + 49152 + off, Bl + gb);
        }
        cp_commit();
    };

    load_stage(0, 0);

    const int a_row = (lane & 15);
    const int a_col16 = (lane >> 4) << 4;
    const int b_grp = lane >> 3;
    const int b_row = ((b_grp >> 1) << 3) + (lane & 7);
    const int b_col16 = (b_grp & 1) << 4;

    for (int c = 0; c < nch; c++) {
        const int st = c & 1;
        if (c + 1 < nch) { load_stage(c + 1, st ^ 1); cp_wait1(); }
        else             { cp_wait0(); }
        __syncthreads();

        const uint32_t a_b  = sb + st * STG;
        const uint32_t bh_b = a_b + 32768;
        const uint32_t bl_b = a_b + 49152;

        #pragma unroll
        for (int ks = 0; ks < 4; ks++) {
            const int kb = ks * 32;
            uint32_t fa[4][4];
            #pragma unroll
            for (int mt = 0; mt < 4; mt++) {
                int row = wm * 64 + mt * 16 + a_row;
                uint32_t off = SW128(row * 128 + kb + a_col16);
                ldsm_x4(fa[mt], a_b + off);
            }
            // pass 1: A * Bh — stream one B fragment at a time (4 live regs)
            #pragma unroll
            for (int nb = 0; nb < 4; nb++) {
                uint32_t fb[4];
                int row = wn * 64 + nb * 16 + b_row;
                uint32_t off = SW128(row * 128 + kb + b_col16);
                ldsm_x4(fb, bh_b + off);
                #pragma unroll
                for (int mt = 0; mt < 4; mt++) {
                    mma16816(acc[mt][2 * nb],     fa[mt], fb[0], fb[1]);
                    mma16816(acc[mt][2 * nb + 1], fa[mt], fb[2], fb[3]);
                }
            }
            // pass 2: A * Bl
            #pragma unroll
            for (int nb = 0; nb < 4; nb++) {
                uint32_t fb[4];
                int row = wn * 64 + nb * 16 + b_row;
                uint32_t off = SW128(row * 128 + kb + b_col16);
                ldsm_x4(fb, bl_b + off);
                #pragma unroll
                for (int mt = 0; mt < 4; mt++) {
                    mma16816(acc[mt][2 * nb],     fa[mt], fb[0], fb[1]);
                    mma16816(acc[mt][2 * nb + 1], fa[mt], fb[2], fb[3]);
                }
            }
        }
        __syncthreads();
    }

    #pragma unroll
    for (int mt = 0; mt < 4; mt++) {
        #pragma unroll
        for (int nt = 0; nt < 8; nt++) {
            int r0  = bm + wm * 64 + mt * 16 + (lane >> 2);
            int col = bn + wn * 64 + nt * 8 + ((lane & 3) << 1);
            float bi0 = bias[col], bi1 = bias[col + 1];
            #pragma unroll
            for (int half_ = 0; half_ < 2; half_++) {
                size_t row = r0 + half_ * 8;
                float v0 = acc[mt][nt][half_ * 2 + 0] + bi0;
                float v1 = acc[mt][nt][half_ * 2 + 1] + bi1;
                if (GELU) { v0 = gelu_exact(v0); v1 = gelu_exact(v1); }
                if (OUTF32) {
                    float2 o2 = make_float2(v0, v1);
                    *(float2*)&Cf[row * ldc + col] = o2;
                } else if (OUTHILO) {
                    __half h0, l0, h1, l1;
                    split_h16(v0, h0, l0);
                    split_h16(v1, h1, l1);
                    *(uint32_t*)&Ch[row * ldc + col] = pack_h16(h0, h1);
                    *(uint32_t*)&Cl[row * ldc + col] = pack_h16(l0, l1);
                } else {
                    *(uint32_t*)&Ch[row * ldc + col] =
                        pack_h16(__float2half_rn(v0), __float2half_rn(v1));
                }
            }
        }
    }
}

// ---------------------------------------------------------------------------
// Tensor-core causal flash attention.
// QK^T: 3-pass fp16 (QhKh + QhKl + QlKh); PV: 2-pass fp16 (P*(Vh+Vl)).
// grid (32, 16, 2) qt reversed; 128 threads = 4 warps, warp = m16 x n64.
// ---------------------------------------------------------------------------
#define ATT_SMEM (16384 + 2 * 32768)

__global__ __launch_bounds__(128, 1)
void attn_mma_kernel(const __half* __restrict__ QKVh,
                     const __half* __restrict__ QKVl,
                     __half* __restrict__ y) {
    extern __shared__ char smem[];
    const uint32_t sb = smem_u32(smem);
    const int qt = (int)gridDim.x - 1 - (int)blockIdx.x;
    const int h = blockIdx.y, b = blockIdx.z;
    const int tid = threadIdx.x, lane = tid & 31, wm = tid >> 5;
    const int base = b * TSEQ;
    const size_t qstride = 3 * DMODEL;

    const uint32_t sQh = sb, sQl = sb + 8192;

    #pragma unroll
    for (int i = 0; i < 4; i++) {
        int id = tid + i * 128;
        int row = id >> 3, c = id & 7;
        uint32_t off = SW128(row * 128 + c * 16);
        size_t g = (size_t)(base + qt * 64 + row) * qstride + h * HD + c * 8;
        cp16(sQh + off, QKVh + g);
        cp16(sQl + off, QKVl + g);
    }
    auto load_kv = [&](int kt, int s) {
        uint32_t kb_ = sb + 16384 + s * 32768;
        #pragma unroll
        for (int i = 0; i < 4; i++) {
            int id = tid + i * 128;
            int row = id >> 3, c = id & 7;
            uint32_t off = SW128(row * 128 + c * 16);
            size_t gk = (size_t)(base + kt * 64 + row) * qstride + DMODEL + h * HD + c * 8;
            size_t gv = gk + DMODEL;
            cp16(kb_ + off,          QKVh + gk);
            cp16(kb_ + 8192 + off,   QKVl + gk);
            cp16(kb_ + 16384 + off,  QKVh + gv);
            cp16(kb_ + 24576 + off,  QKVl + gv);
        }
    };
    load_kv(0, 0);
    cp_commit();

    float oacc[8][4];
    #pragma unroll
    for (int i = 0; i < 8; i++)
        #pragma unroll
        for (int j = 0; j < 4; j++) oacc[i][j] = 0.f;
    float m0 = -INFINITY, m1 = -INFINITY, l0 = 0.f, l1 = 0.f;

    for (int kt = 0; kt <= qt; kt++) {
        const int st = kt & 1;
        if (kt < qt) { load_kv(kt + 1, st ^ 1); cp_commit(); cp_wait1(); }
        else         { cp_wait0(); }
        __syncthreads();

        const uint32_t sKh = sb + 16384 + st * 32768;
        const uint32_t sKl = sKh + 8192;
        const uint32_t sVh = sKh + 16384;
        const uint32_t sVl = sKh + 24576;

        float sacc[8][4];
        #pragma unroll
        for (int i = 0; i < 8; i++)
            #pragma unroll
            for (int j = 0; j < 4; j++) sacc[i][j] = 0.f;

        #pragma unroll
        for (int ks = 0; ks < 4; ks++) {
            uint32_t qh[4], ql[4];
            {
                int r = wm * 16 + (lane & 15);
                int byt = ks * 32 + ((lane >> 4) << 4);
                uint32_t off = SW128(r * 128 + byt);
                ldsm_x4(qh, sQh + off);
                ldsm_x4(ql, sQl + off);
            }
            #pragma unroll
            for (int nb2 = 0; nb2 < 4; nb2++) {
                uint32_t kh[4], kl[4];
                int grp = lane >> 3;
                int r = nb2 * 16 + ((grp >> 1) << 3) + (lane & 7);
                int byt = ks * 32 + ((grp & 1) << 4);
                uint32_t off = SW128(r * 128 + byt);
                ldsm_x4(kh, sKh + off);
                ldsm_x4(kl, sKl + off);
                mma16816(sacc[2 * nb2],     qh, kh[0], kh[1]);
                mma16816(sacc[2 * nb2],     qh, kl[0], kl[1]);
                mma16816(sacc[2 * nb2],     ql, kh[0], kh[1]);
                mma16816(sacc[2 * nb2 + 1], qh, kh[2], kh[3]);
                mma16816(sacc[2 * nb2 + 1], qh, kl[2], kl[3]);
                mma16816(sacc[2 * nb2 + 1], ql, kh[2], kh[3]);
            }
        }

        const bool diag = (kt == qt);
        const int lr0 = wm * 16 + (lane >> 2);
        #pragma unroll
        for (int nt = 0; nt < 8; nt++) {
            int c0 = nt * 8 + 2 * (lane & 3);
            #pragma unroll
            for (int j = 0; j < 4; j++) {
                float v = sacc[nt][j] * 0.125f;
                if (diag && (c0 + (j & 1)) > (lr0 + (j >> 1) * 8)) v = -1e30f;
                sacc[nt][j] = v;
            }
        }

        float r0m = -1e30f, r1m = -1e30f;
        #pragma unroll
        for (int nt = 0; nt < 8; nt++) {
            r0m = fmaxf(r0m, fmaxf(sacc[nt][0], sacc[nt][1]));
            r1m = fmaxf(r1m, fmaxf(sacc[nt][2], sacc[nt][3]));
        }
        r0m = fmaxf(r0m, __shfl_xor_sync(0xffffffffu, r0m, 1));
        r0m = fmaxf(r0m, __shfl_xor_sync(0xffffffffu, r0m, 2));
        r1m = fmaxf(r1m, __shfl_xor_sync(0xffffffffu, r1m, 1));
        r1m = fmaxf(r1m, __shfl_xor_sync(0xffffffffu, r1m, 2));
        float m0n = fmaxf(m0, r0m), m1n = fmaxf(m1, r1m);
        float cr0 = __expf(m0 - m0n), cr1 = __expf(m1 - m1n);
        m0 = m0n; m1 = m1n;
        l0 *= cr0; l1 *= cr1;
        #pragma unroll
        for (int nt = 0; nt < 8; nt++) {
            oacc[nt][0] *= cr0; oacc[nt][1] *= cr0;
            oacc[nt][2] *= cr1; oacc[nt][3] *= cr1;
        }
        float ps0 = 0.f, ps1 = 0.f;
        #pragma unroll
        for (int nt = 0; nt < 8; nt++) {
            float p0 = __expf(sacc[nt][0] - m0);
            float p1 = __expf(sacc[nt][1] - m0);
            float p2 = __expf(sacc[nt][2] - m1);
            float p3 = __expf(sacc[nt][3] - m1);
            ps0 += p0 + p1; ps1 += p2 + p3;
            sacc[nt][0] = p0; sacc[nt][1] = p1; sacc[nt][2] = p2; sacc[nt][3] = p3;
        }
        l0 += ps0; l1 += ps1;

        // --- O += P (Vh + Vl), P in single fp16 ---
        #pragma unroll
        for (int s = 0; s < 4; s++) {
            uint32_t aP[4];
            #pragma unroll
            for (int half_ = 0; half_ < 2; half_++) {
                int blk = 2 * s + half_;
                aP[2 * half_ + 0] = pack_h16(__float2half_rn(sacc[blk][0]),
                                             __float2half_rn(sacc[blk][1]));
                aP[2 * half_ + 1] = pack_h16(__float2half_rn(sacc[blk][2]),
                                             __float2half_rn(sacc[blk][3]));
            }
            #pragma unroll
            for (int dd = 0; dd < 4; dd++) {
                uint32_t vh[4], vl[4];
                int grp = lane >> 3;
                int key = s * 16 + (grp & 1) * 8 + (lane & 7);
                int byt = dd * 32 + ((grp >> 1) << 4);
                uint32_t off = SW128(key * 128 + byt);
                ldsm_x4_t(vh, sVh + off);
                ldsm_x4_t(vl, sVl + off);
                mma16816(oacc[2 * dd],     aP, vh[0], vh[1]);
                mma16816(oacc[2 * dd],     aP, vl[0], vl[1]);
                mma16816(oacc[2 * dd + 1], aP, vh[2], vh[3]);
                mma16816(oacc[2 * dd + 1], aP, vl[2], vl[3]);
            }
        }
        __syncthreads();
    }

    l0 += __shfl_xor_sync(0xffffffffu, l0, 1);
    l0 += __shfl_xor_sync(0xffffffffu, l0, 2);
    l1 += __shfl_xor_sync(0xffffffffu, l1, 1);
    l1 += __shfl_xor_sync(0xffffffffu, l1, 2);
    float inv0 = 1.0f / l0, inv1 = 1.0f / l1;

    const size_t gr0 = (size_t)(base + qt * 64 + wm * 16 + (lane >> 2));
    const int colb = h * HD + 2 * (lane & 3);
    #pragma unroll
    for (int nt = 0; nt < 8; nt++) {
        int col = colb + nt * 8;
        *(uint32_t*)&y[gr0 * DMODEL + col] =
            pack_h16(__float2half_rn(oacc[nt][0] * inv0),
                     __float2half_rn(oacc[nt][1] * inv0));
        *(uint32_t*)&y[(gr0 + 8) * DMODEL + col] =
            pack_h16(__float2half_rn(oacc[nt][2] * inv1),
                     __float2half_rn(oacc[nt][3] * inv1));
    }
}

// ---------------------------------------------------------------------------
// Launch
// ---------------------------------------------------------------------------
extern "C" void kernel_launch(void* const* d_in, const int* in_sizes, int n_in,
                              void* d_out, int out_size) {
    const float* z      = (const float*)d_in[0];
    const float* t      = (const float*)d_in[1];
    const float* w_t1   = (const float*)d_in[2];
    const float* b_t1   = (const float*)d_in[3];
    const float* w_t2   = (const float*)d_in[4];
    const float* b_t2   = (const float*)d_in[5];
    const float* ln_a_w = (const float*)d_in[6];
    const float* ln_a_b = (const float*)d_in[7];
    const float* w_attn = (const float*)d_in[8];
    const float* b_attn = (const float*)d_in[9];
    const float* w_proj = (const float*)d_in[10];
    const float* b_proj = (const float*)d_in[11];
    const float* ln_m_w = (const float*)d_in[12];
    const float* ln_m_b = (const float*)d_in[13];
    const float* w_fc   = (const float*)d_in[14];
    const float* b_fc   = (const float*)d_in[15];
    const float* w_fc2  = (const float*)d_in[16];
    const float* b_fc2  = (const float*)d_in[17];
    float* out = (float*)d_out;
    (void)n_in; (void)in_sizes; (void)out_size;

    float* gh;
    __half *gA, *gGh, *gGl, *gBh, *gBl;
    cudaGetSymbolAddress((void**)&gh,  g_h);
    cudaGetSymbolAddress((void**)&gA,  g_A);
    cudaGetSymbolAddress((void**)&gGh, g_Gh);
    cudaGetSymbolAddress((void**)&gGl, g_Gl);
    cudaGetSymbolAddress((void**)&gBh, g_Bh);
    cudaGetSymbolAddress((void**)&gBl, g_Bl);

    cudaFuncSetAttribute(mma_gemm<false, true, false>,
                         cudaFuncAttributeMaxDynamicSharedMemorySize, SM_TOT);
    cudaFuncSetAttribute(mma_gemm<true, false, false>,
                         cudaFuncAttributeMaxDynamicSharedMemorySize, SM_TOT);
    cudaFuncSetAttribute(mma_gemm<false, false, true>,
                         cudaFuncAttributeMaxDynamicSharedMemorySize, SM_TOT);
    cudaFuncSetAttribute(attn_mma_kernel,
                         cudaFuncAttributeMaxDynamicSharedMemorySize, ATT_SMEM);

    // 1. time embedding
    time_mlp_kernel<<<BATCH, TE>>>(t, w_t1, b_t1, w_t2, b_t2);

    // 2. LN(concat(z, temb)) -> fp16 [4096,1088]
    ln_concat_kernel<<<NTOK, 256>>>(z, ln_a_w, ln_a_b, gA);

    // 3. qkv GEMM -> fp16 hi/lo [4096,3072] in g_G
    wconv_kernel<<<dim3(3 * DMODEL / 32, CDIM / 32), dim3(32, 8)>>>(w_attn, gBh, gBl, CDIM, 3 * DMODEL);
    mma_gemm<false, false, true><<<dim3(3 * DMODEL / 128, NTOK / 256), 256, SM_TOT>>>(
        gA, CDIM, gBh, gBl, b_attn, nullptr, gGh, gGl, 3 * DMODEL, CDIM);

    // 4. tensor-core attention -> y fp16 in g_A (stride 1024)
    attn_mma_kernel<<<dim3(TSEQ / 64, NHEAD, BATCH), 128, ATT_SMEM>>>(gGh, gGl, gA);

    // 5. proj GEMM -> fp32 g_h
    wconv_kernel<<<dim3(DMODEL / 32, DMODEL / 32), dim3(32, 8)>>>(w_proj, gBh, gBl, DMODEL, DMODEL);
    mma_gemm<false, true, false><<<dim3(DMODEL / 128, NTOK / 256), 256, SM_TOT>>>(
        gA, DMODEL, gBh, gBl, b_proj, gh, nullptr, nullptr, DMODEL, DMODEL);

    // 6. LN(concat(h, temb)) -> fp16 [4096,1088]
    ln_concat_kernel<<<NTOK, 256>>>(gh, ln_m_w, ln_m_b, gA);

    // 7. fc GEMM + GELU -> single fp16 [4096,4096] in g_Gh
    wconv_kernel<<<dim3(4 * DMODEL / 32, CDIM / 32), dim3(32, 8)>>>(w_fc, gBh, gBl, CDIM, 4 * DMODEL);
    mma_gemm<true, false, false><<<dim3(4 * DMODEL / 128, NTOK / 256), 256, SM_TOT>>>(
        gA, CDIM, gBh, gBl, b_fc, nullptr, gGh, nullptr, 4 * DMODEL, CDIM);

    // 8. fc2 GEMM -> fp32 out
    wconv_kernel<<<dim3(DMODEL / 32, 4 * DMODEL / 32), dim3(32, 8)>>>(w_fc2, gBh, gBl, 4 * DMODEL, DMODEL);
    mma_gemm<false, true, false><<<dim3(DMODEL / 128, NTOK / 256), 256, SM_TOT>>>(
        gGh, 4 * DMODEL, gBh, gBl, b_fc2, out, nullptr, nullptr, DMODEL, 4 * DMODEL);
}

// round 16
// speedup vs baseline: 1.2816x; 1.2786x over previous
#include <cuda_runtime.h>
#include <cuda_fp16.h>
#include <cstdint>
#include <math.h>

// ---------------------------------------------------------------------------
// Problem constants
// ---------------------------------------------------------------------------
#define BATCH 2
#define TSEQ  2048
#define DMODEL 1024
#define TE    64
#define CDIM  1088
#define NHEAD 16
#define HD    64
#define NTOK  (BATCH * TSEQ)  // 4096
#define EPSLN 1e-5f

// ---------------------------------------------------------------------------
// Scratch (static device arrays; no allocation anywhere)
// ---------------------------------------------------------------------------
__device__ float g_temb[BATCH * TE];
__device__ float g_h[NTOK * DMODEL];                 // proj out fp32
__device__ __half g_A[NTOK * CDIM];                  // LN out / attn y (single fp16)
__device__ __half g_Gh[NTOK * 4 * DMODEL];           // qkv hi, later gelu (single)
__device__ __half g_Gl[NTOK * 4 * DMODEL];           // qkv lo
__device__ __half g_Bh[4096 * 1088];                 // weight hi (transposed)
__device__ __half g_Bl[4096 * 1088];                 // weight lo

__device__ __forceinline__ float gelu_exact(float x) {
    return 0.5f * x * (1.0f + erff(x * 0.70710678118654752440f));
}
__device__ __forceinline__ void split_h16(float v, __half& h, __half& l) {
    h = __float2half_rn(v);
    l = __float2half_rn(v - __half2float(h));
}
__device__ __forceinline__ uint32_t pack_h16(__half a, __half b) {
    __half2 p; p.x = a; p.y = b;
    return *(uint32_t*)&p;
}

// ---------------------------------------------------------------------------
// PTX helpers (baseline PTX only: cp.async, ldmatrix, mma.sync)
// ---------------------------------------------------------------------------
__device__ __forceinline__ uint32_t smem_u32(const void* p) {
    uint32_t a;
    asm("{ .reg .u64 t; cvta.to.shared.u64 t, %1; cvt.u32.u64 %0, t; }" : "=r"(a) : "l"(p));
    return a;
}
#define SW128(off) ((off) ^ (((off) >> 3) & 0x70))

__device__ __forceinline__ void cp16(uint32_t dst, const void* src) {
    asm volatile("cp.async.cg.shared.global [%0], [%1], 16;" :: "r"(dst), "l"(src) : "memory");
}
__device__ __forceinline__ void cp_commit() { asm volatile("cp.async.commit_group;" ::: "memory"); }
__device__ __forceinline__ void cp_wait1() { asm volatile("cp.async.wait_group 1;" ::: "memory"); }
__device__ __forceinline__ void cp_wait0() { asm volatile("cp.async.wait_group 0;" ::: "memory"); }

__device__ __forceinline__ void ldsm_x4(uint32_t (&r)[4], uint32_t addr) {
    asm volatile("ldmatrix.sync.aligned.m8n8.x4.shared.b16 {%0,%1,%2,%3}, [%4];"
        : "=r"(r[0]), "=r"(r[1]), "=r"(r[2]), "=r"(r[3]) : "r"(addr));
}
__device__ __forceinline__ void ldsm_x4_t(uint32_t (&r)[4], uint32_t addr) {
    asm volatile("ldmatrix.sync.aligned.m8n8.x4.trans.shared.b16 {%0,%1,%2,%3}, [%4];"
        : "=r"(r[0]), "=r"(r[1]), "=r"(r[2]), "=r"(r[3]) : "r"(addr));
}
__device__ __forceinline__ void mma16816(float (&d)[4], const uint32_t (&a)[4],
                                         uint32_t b0, uint32_t b1) {
    asm volatile("mma.sync.aligned.m16n8k16.row.col.f32.f16.f16.f32 "
        "{%0,%1,%2,%3}, {%4,%5,%6,%7}, {%8,%9}, {%0,%1,%2,%3};"
        : "+f"(d[0]), "+f"(d[1]), "+f"(d[2]), "+f"(d[3])
        : "r"(a[0]), "r"(a[1]), "r"(a[2]), "r"(a[3]), "r"(b0), "r"(b1));
}

// ---------------------------------------------------------------------------
// Time MLP
// ---------------------------------------------------------------------------
__global__ void time_mlp_kernel(const float* __restrict__ t,
                                const float* __restrict__ w1, const float* __restrict__ b1,
                                const float* __restrict__ w2, const float* __restrict__ b2) {
    int b = blockIdx.x;
    int e = threadIdx.x;
    __shared__ float h1[TE];
    h1[e] = gelu_exact(t[b] * w1[e] + b1[e]);
    __syncthreads();
    float acc = b2[e];
    #pragma unroll 8
    for (int i = 0; i < TE; i++) acc += h1[i] * w2[i * TE + e];
    g_temb[b * TE + e] = acc;
}

// ---------------------------------------------------------------------------
// LayerNorm over concat([x(1024), t_emb(64)]) -> single fp16 [NTOK, 1088]
// ---------------------------------------------------------------------------
__global__ void ln_concat_kernel(const float* __restrict__ x,
                                 const float* __restrict__ w,
                                 const float* __restrict__ bias,
                                 __half* __restrict__ oh) {
    const int token = blockIdx.x;
    const int b = token >> 11;
    const int tid = threadIdx.x;

    __shared__ float xs[CDIM];
    __shared__ float red[16];

    float sum = 0.f, sumsq = 0.f;
    for (int c = tid; c < CDIM; c += 256) {
        float v = (c < DMODEL) ? x[(size_t)token * DMODEL + c] : g_temb[b * TE + (c - DMODEL)];
        xs[c] = v;
        sum += v;
        sumsq += v * v;
    }
    #pragma unroll
    for (int o = 16; o > 0; o >>= 1) {
        sum   += __shfl_xor_sync(0xffffffffu, sum, o);
        sumsq += __shfl_xor_sync(0xffffffffu, sumsq, o);
    }
    int warp = tid >> 5, lane = tid & 31;
    if (lane == 0) { red[warp] = sum; red[warp + 8] = sumsq; }
    __syncthreads();
    if (tid == 0) {
        float s = 0.f, sq = 0.f;
        #pragma unroll
        for (int i = 0; i < 8; i++) { s += red[i]; sq += red[i + 8]; }
        float mu = s * (1.0f / CDIM);
        float var = sq * (1.0f / CDIM) - mu * mu;
        red[0] = mu;
        red[1] = rsqrtf(var + EPSLN);
    }
    __syncthreads();
    float mu = red[0], rs = red[1];
    for (int c = tid; c < CDIM; c += 256) {
        float v = (xs[c] - mu) * rs * w[c] + bias[c];
        oh[(size_t)token * CDIM + c] = __float2half_rn(v);
    }
}

// ---------------------------------------------------------------------------
// Weight convert + transpose: w[K,N] fp32 -> oh/ol[N,K] fp16 hi/lo
// ---------------------------------------------------------------------------
__global__ void wconv_kernel(const float* __restrict__ w,
                             __half* __restrict__ oh, __half* __restrict__ ol,
                             int K, int N) {
    __shared__ float tile[32][33];
    int nb = blockIdx.x * 32, kb = blockIdx.y * 32;
    int tx = threadIdx.x, ty = threadIdx.y;
    #pragma unroll
    for (int i = 0; i < 32; i += 8)
        tile[ty + i][tx] = w[(size_t)(kb + ty + i) * N + nb + tx];
    __syncthreads();
    #pragma unroll
    for (int i = 0; i < 32; i += 8) {
        float v = tile[tx][ty + i];
        __half h, l;
        split_h16(v, h, l);
        oh[(size_t)(nb + ty + i) * K + kb + tx] = h;
        if (ol) ol[(size_t)(nb + ty + i) * K + kb + tx] = l;
    }
}

// ---------------------------------------------------------------------------
// mma.sync fp16 GEMM: C[M,N] = A[M,K] @ B^T  (B stored [N,K]).
// TWOB=true:  B = Bh + Bl (2 passes, compensated weights).
// TWOB=false: B = Bh only (1 pass) — used for fc/fc2 where the extra
//             2^-11 weight-rounding term fits the error budget.
// CTA 256x128, BK=64, 256 threads (8 warps 4Mx2N), warp tile m64xn64.
// ---------------------------------------------------------------------------
#define STG 65536
#define SM_TOT (2 * STG)

template <bool GELU, bool OUTF32, bool OUTHILO, bool TWOB>
__global__ __launch_bounds__(256, 1)
void mma_gemm(const __half* __restrict__ A, int lda,
              const __half* __restrict__ Bh, const __half* __restrict__ Bl,
              const float* __restrict__ bias,
              float* __restrict__ Cf, __half* __restrict__ Ch, __half* __restrict__ Cl,
              int ldc, int K) {
    extern __shared__ char smem[];
    const uint32_t sb = smem_u32(smem);
    const int tid = threadIdx.x;
    const int lane = tid & 31;
    const int wid = tid >> 5;
    const int wm = wid & 3;        // rows wm*64..+63
    const int wn = wid >> 2;       // cols wn*64..+63
    const int bm = blockIdx.y * 256;
    const int bn = blockIdx.x * 128;
    const int nch = K >> 6;

    float acc[4][8][4];
    #pragma unroll
    for (int i = 0; i < 4; i++)
        #pragma unroll
        for (int j = 0; j < 8; j++)
            #pragma unroll
            for (int q = 0; q < 4; q++) acc[i][j][q] = 0.f;

    auto load_stage = [&](int c, int s) {
        const int k0 = c * 64;
        const uint32_t base = sb + s * STG;
        // A: 256 rows x 8 x 16B
        #pragma unroll
        for (int i = 0; i < 8; i++) {
            int id = tid + i * 256;          // 0..2047
            int row = id >> 3;
            int c16 = id & 7;
            uint32_t off = SW128(row * 128 + c16 * 16);
            cp16(base + off, A + (size_t)(bm + row) * lda + k0 + c16 * 8);
        }
        // B hi (+ lo if TWOB): 128 rows x 8 x 16B each
        #pragma unroll
        for (int i = 0; i < 4; i++) {
            int id = tid + i * 256;          // 0..1023
            int row = id >> 3;
            int c16 = id & 7;
            uint32_t off = SW128(row * 128 + c16 * 16);
            const size_t gb = (size_t)(bn + row) * K + k0 + c16 * 8;
            cp16(base + 32768 + off, Bh + gb);
            if (TWOB) cp16(base + 49152 + off, Bl + gb);
        }
        cp_commit();
    };

    load_stage(0, 0);

    const int a_row = (lane & 15);
    const int a_col16 = (lane >> 4) << 4;
    const int b_grp = lane >> 3;
    const int b_row = ((b_grp >> 1) << 3) + (lane & 7);
    const int b_col16 = (b_grp & 1) << 4;

    for (int c = 0; c < nch; c++) {
        const int st = c & 1;
        if (c + 1 < nch) { load_stage(c + 1, st ^ 1); cp_wait1(); }
        else             { cp_wait0(); }
        __syncthreads();

        const uint32_t a_b  = sb + st * STG;
        const uint32_t bh_b = a_b + 32768;
        const uint32_t bl_b = a_b + 49152;

        #pragma unroll
        for (int ks = 0; ks < 4; ks++) {
            const int kb = ks * 32;
            uint32_t fa[4][4];
            #pragma unroll
            for (int mt = 0; mt < 4; mt++) {
                int row = wm * 64 + mt * 16 + a_row;
                uint32_t off = SW128(row * 128 + kb + a_col16);
                ldsm_x4(fa[mt], a_b + off);
            }
            uint32_t fbh[4][4];
            #pragma unroll
            for (int nb = 0; nb < 4; nb++) {
                int row = wn * 64 + nb * 16 + b_row;
                uint32_t off = SW128(row * 128 + kb + b_col16);
                ldsm_x4(fbh[nb], bh_b + off);
            }
            #pragma unroll
            for (int mt = 0; mt < 4; mt++)
                #pragma unroll
                for (int nt = 0; nt < 8; nt++)
                    mma16816(acc[mt][nt], fa[mt],
                             fbh[nt >> 1][(nt & 1) * 2], fbh[nt >> 1][(nt & 1) * 2 + 1]);
            if (TWOB) {
                uint32_t fbl[4][4];
                #pragma unroll
                for (int nb = 0; nb < 4; nb++) {
                    int row = wn * 64 + nb * 16 + b_row;
                    uint32_t off = SW128(row * 128 + kb + b_col16);
                    ldsm_x4(fbl[nb], bl_b + off);
                }
                #pragma unroll
                for (int mt = 0; mt < 4; mt++)
                    #pragma unroll
                    for (int nt = 0; nt < 8; nt++)
                        mma16816(acc[mt][nt], fa[mt],
                                 fbl[nt >> 1][(nt & 1) * 2], fbl[nt >> 1][(nt & 1) * 2 + 1]);
            }
        }
        __syncthreads();
    }

    #pragma unroll
    for (int mt = 0; mt < 4; mt++) {
        #pragma unroll
        for (int nt = 0; nt < 8; nt++) {
            int r0  = bm + wm * 64 + mt * 16 + (lane >> 2);
            int col = bn + wn * 64 + nt * 8 + ((lane & 3) << 1);
            float bi0 = bias[col], bi1 = bias[col + 1];
            #pragma unroll
            for (int half_ = 0; half_ < 2; half_++) {
                size_t row = r0 + half_ * 8;
                float v0 = acc[mt][nt][half_ * 2 + 0] + bi0;
                float v1 = acc[mt][nt][half_ * 2 + 1] + bi1;
                if (GELU) { v0 = gelu_exact(v0); v1 = gelu_exact(v1); }
                if (OUTF32) {
                    float2 o2 = make_float2(v0, v1);
                    *(float2*)&Cf[row * ldc + col] = o2;
                } else if (OUTHILO) {
                    __half h0, l0, h1, l1;
                    split_h16(v0, h0, l0);
                    split_h16(v1, h1, l1);
                    *(uint32_t*)&Ch[row * ldc + col] = pack_h16(h0, h1);
                    *(uint32_t*)&Cl[row * ldc + col] = pack_h16(l0, l1);
                } else {
                    *(uint32_t*)&Ch[row * ldc + col] =
                        pack_h16(__float2half_rn(v0), __float2half_rn(v1));
                }
            }
        }
    }
}

// ---------------------------------------------------------------------------
// Tensor-core causal flash attention.
// QK^T: 3-pass fp16 (QhKh + QhKl + QlKh); PV: 2-pass fp16 (P*(Vh+Vl)).
// grid (32, 16, 2) qt reversed; 128 threads = 4 warps, warp = m16 x n64.
// ---------------------------------------------------------------------------
#define ATT_SMEM (16384 + 2 * 32768)

__global__ __launch_bounds__(128, 1)
void attn_mma_kernel(const __half* __restrict__ QKVh,
                     const __half* __restrict__ QKVl,
                     __half* __restrict__ y) {
    extern __shared__ char smem[];
    const uint32_t sb = smem_u32(smem);
    const int qt = (int)gridDim.x - 1 - (int)blockIdx.x;
    const int h = blockIdx.y, b = blockIdx.z;
    const int tid = threadIdx.x, lane = tid & 31, wm = tid >> 5;
    const int base = b * TSEQ;
    const size_t qstride = 3 * DMODEL;

    const uint32_t sQh = sb, sQl = sb + 8192;

    #pragma unroll
    for (int i = 0; i < 4; i++) {
        int id = tid + i * 128;
        int row = id >> 3, c = id & 7;
        uint32_t off = SW128(row * 128 + c * 16);
        size_t g = (size_t)(base + qt * 64 + row) * qstride + h * HD + c * 8;
        cp16(sQh + off, QKVh + g);
        cp16(sQl + off, QKVl + g);
    }
    auto load_kv = [&](int kt, int s) {
        uint32_t kb_ = sb + 16384 + s * 32768;
        #pragma unroll
        for (int i = 0; i < 4; i++) {
            int id = tid + i * 128;
            int row = id >> 3, c = id & 7;
            uint32_t off = SW128(row * 128 + c * 16);
            size_t gk = (size_t)(base + kt * 64 + row) * qstride + DMODEL + h * HD + c * 8;
            size_t gv = gk + DMODEL;
            cp16(kb_ + off,          QKVh + gk);
            cp16(kb_ + 8192 + off,   QKVl + gk);
            cp16(kb_ + 16384 + off,  QKVh + gv);
            cp16(kb_ + 24576 + off,  QKVl + gv);
        }
    };
    load_kv(0, 0);
    cp_commit();

    float oacc[8][4];
    #pragma unroll
    for (int i = 0; i < 8; i++)
        #pragma unroll
        for (int j = 0; j < 4; j++) oacc[i][j] = 0.f;
    float m0 = -INFINITY, m1 = -INFINITY, l0 = 0.f, l1 = 0.f;

    for (int kt = 0; kt <= qt; kt++) {
        const int st = kt & 1;
        if (kt < qt) { load_kv(kt + 1, st ^ 1); cp_commit(); cp_wait1(); }
        else         { cp_wait0(); }
        __syncthreads();

        const uint32_t sKh = sb + 16384 + st * 32768;
        const uint32_t sKl = sKh + 8192;
        const uint32_t sVh = sKh + 16384;
        const uint32_t sVl = sKh + 24576;

        float sacc[8][4];
        #pragma unroll
        for (int i = 0; i < 8; i++)
            #pragma unroll
            for (int j = 0; j < 4; j++) sacc[i][j] = 0.f;

        #pragma unroll
        for (int ks = 0; ks < 4; ks++) {
            uint32_t qh[4], ql[4];
            {
                int r = wm * 16 + (lane & 15);
                int byt = ks * 32 + ((lane >> 4) << 4);
                uint32_t off = SW128(r * 128 + byt);
                ldsm_x4(qh, sQh + off);
                ldsm_x4(ql, sQl + off);
            }
            #pragma unroll
            for (int nb2 = 0; nb2 < 4; nb2++) {
                uint32_t kh[4], kl[4];
                int grp = lane >> 3;
                int r = nb2 * 16 + ((grp >> 1) << 3) + (lane & 7);
                int byt = ks * 32 + ((grp & 1) << 4);
                uint32_t off = SW128(r * 128 + byt);
                ldsm_x4(kh, sKh + off);
                ldsm_x4(kl, sKl + off);
                mma16816(sacc[2 * nb2],     qh, kh[0], kh[1]);
                mma16816(sacc[2 * nb2],     qh, kl[0], kl[1]);
                mma16816(sacc[2 * nb2],     ql, kh[0], kh[1]);
                mma16816(sacc[2 * nb2 + 1], qh, kh[2], kh[3]);
                mma16816(sacc[2 * nb2 + 1], qh, kl[2], kl[3]);
                mma16816(sacc[2 * nb2 + 1], ql, kh[2], kh[3]);
            }
        }

        const bool diag = (kt == qt);
        const int lr0 = wm * 16 + (lane >> 2);
        #pragma unroll
        for (int nt = 0; nt < 8; nt++) {
            int c0 = nt * 8 + 2 * (lane & 3);
            #pragma unroll
            for (int j = 0; j < 4; j++) {
                float v = sacc[nt][j] * 0.125f;
                if (diag && (c0 + (j & 1)) > (lr0 + (j >> 1) * 8)) v = -1e30f;
                sacc[nt][j] = v;
            }
        }

        float r0m = -1e30f, r1m = -1e30f;
        #pragma unroll
        for (int nt = 0; nt < 8; nt++) {
            r0m = fmaxf(r0m, fmaxf(sacc[nt][0], sacc[nt][1]));
            r1m = fmaxf(r1m, fmaxf(sacc[nt][2], sacc[nt][3]));
        }
        r0m = fmaxf(r0m, __shfl_xor_sync(0xffffffffu, r0m, 1));
        r0m = fmaxf(r0m, __shfl_xor_sync(0xffffffffu, r0m, 2));
        r1m = fmaxf(r1m, __shfl_xor_sync(0xffffffffu, r1m, 1));
        r1m = fmaxf(r1m, __shfl_xor_sync(0xffffffffu, r1m, 2));
        float m0n = fmaxf(m0, r0m), m1n = fmaxf(m1, r1m);
        float cr0 = __expf(m0 - m0n), cr1 = __expf(m1 - m1n);
        m0 = m0n; m1 = m1n;
        l0 *= cr0; l1 *= cr1;
        #pragma unroll
        for (int nt = 0; nt < 8; nt++) {
            oacc[nt][0] *= cr0; oacc[nt][1] *= cr0;
            oacc[nt][2] *= cr1; oacc[nt][3] *= cr1;
        }
        float ps0 = 0.f, ps1 = 0.f;
        #pragma unroll
        for (int nt = 0; nt < 8; nt++) {
            float p0 = __expf(sacc[nt][0] - m0);
            float p1 = __expf(sacc[nt][1] - m0);
            float p2 = __expf(sacc[nt][2] - m1);
            float p3 = __expf(sacc[nt][3] - m1);
            ps0 += p0 + p1; ps1 += p2 + p3;
            sacc[nt][0] = p0; sacc[nt][1] = p1; sacc[nt][2] = p2; sacc[nt][3] = p3;
        }
        l0 += ps0; l1 += ps1;

        // --- O += P (Vh + Vl), P in single fp16 ---
        #pragma unroll
        for (int s = 0; s < 4; s++) {
            uint32_t aP[4];
            #pragma unroll
            for (int half_ = 0; half_ < 2; half_++) {
                int blk = 2 * s + half_;
                aP[2 * half_ + 0] = pack_h16(__float2half_rn(sacc[blk][0]),
                                             __float2half_rn(sacc[blk][1]));
                aP[2 * half_ + 1] = pack_h16(__float2half_rn(sacc[blk][2]),
                                             __float2half_rn(sacc[blk][3]));
            }
            #pragma unroll
            for (int dd = 0; dd < 4; dd++) {
                uint32_t vh[4], vl[4];
                int grp = lane >> 3;
                int key = s * 16 + (grp & 1) * 8 + (lane & 7);
                int byt = dd * 32 + ((grp >> 1) << 4);
                uint32_t off = SW128(key * 128 + byt);
                ldsm_x4_t(vh, sVh + off);
                ldsm_x4_t(vl, sVl + off);
                mma16816(oacc[2 * dd],     aP, vh[0], vh[1]);
                mma16816(oacc[2 * dd],     aP, vl[0], vl[1]);
                mma16816(oacc[2 * dd + 1], aP, vh[2], vh[3]);
                mma16816(oacc[2 * dd + 1], aP, vl[2], vl[3]);
            }
        }
        __syncthreads();
    }

    l0 += __shfl_xor_sync(0xffffffffu, l0, 1);
    l0 += __shfl_xor_sync(0xffffffffu, l0, 2);
    l1 += __shfl_xor_sync(0xffffffffu, l1, 1);
    l1 += __shfl_xor_sync(0xffffffffu, l1, 2);
    float inv0 = 1.0f / l0, inv1 = 1.0f / l1;

    const size_t gr0 = (size_t)(base + qt * 64 + wm * 16 + (lane >> 2));
    const int colb = h * HD + 2 * (lane & 3);
    #pragma unroll
    for (int nt = 0; nt < 8; nt++) {
        int col = colb + nt * 8;
        *(uint32_t*)&y[gr0 * DMODEL + col] =
            pack_h16(__float2half_rn(oacc[nt][0] * inv0),
                     __float2half_rn(oacc[nt][1] * inv0));
        *(uint32_t*)&y[(gr0 + 8) * DMODEL + col] =
            pack_h16(__float2half_rn(oacc[nt][2] * inv1),
                     __float2half_rn(oacc[nt][3] * inv1));
    }
}

// ---------------------------------------------------------------------------
// Launch
// ---------------------------------------------------------------------------
extern "C" void kernel_launch(void* const* d_in, const int* in_sizes, int n_in,
                              void* d_out, int out_size) {
    const float* z      = (const float*)d_in[0];
    const float* t      = (const float*)d_in[1];
    const float* w_t1   = (const float*)d_in[2];
    const float* b_t1   = (const float*)d_in[3];
    const float* w_t2   = (const float*)d_in[4];
    const float* b_t2   = (const float*)d_in[5];
    const float* ln_a_w = (const float*)d_in[6];
    const float* ln_a_b = (const float*)d_in[7];
    const float* w_attn = (const float*)d_in[8];
    const float* b_attn = (const float*)d_in[9];
    const float* w_proj = (const float*)d_in[10];
    const float* b_proj = (const float*)d_in[11];
    const float* ln_m_w = (const float*)d_in[12];
    const float* ln_m_b = (const float*)d_in[13];
    const float* w_fc   = (const float*)d_in[14];
    const float* b_fc   = (const float*)d_in[15];
    const float* w_fc2  = (const float*)d_in[16];
    const float* b_fc2  = (const float*)d_in[17];
    float* out = (float*)d_out;
    (void)n_in; (void)in_sizes; (void)out_size;

    float* gh;
    __half *gA, *gGh, *gGl, *gBh, *gBl;
    cudaGetSymbolAddress((void**)&gh,  g_h);
    cudaGetSymbolAddress((void**)&gA,  g_A);
    cudaGetSymbolAddress((void**)&gGh, g_Gh);
    cudaGetSymbolAddress((void**)&gGl, g_Gl);
    cudaGetSymbolAddress((void**)&gBh, g_Bh);
    cudaGetSymbolAddress((void**)&gBl, g_Bl);

    cudaFuncSetAttribute(mma_gemm<false, false, true, true>,
                         cudaFuncAttributeMaxDynamicSharedMemorySize, SM_TOT);
    cudaFuncSetAttribute(mma_gemm<false, true, false, true>,
                         cudaFuncAttributeMaxDynamicSharedMemorySize, SM_TOT);
    cudaFuncSetAttribute(mma_gemm<true, false, false, false>,
                         cudaFuncAttributeMaxDynamicSharedMemorySize, SM_TOT);
    cudaFuncSetAttribute(mma_gemm<false, true, false, false>,
                         cudaFuncAttributeMaxDynamicSharedMemorySize, SM_TOT);
    cudaFuncSetAttribute(attn_mma_kernel,
                         cudaFuncAttributeMaxDynamicSharedMemorySize, ATT_SMEM);

    // 1. time embedding
    time_mlp_kernel<<<BATCH, TE>>>(t, w_t1, b_t1, w_t2, b_t2);

    // 2. LN(concat(z, temb)) -> fp16 [4096,1088]
    ln_concat_kernel<<<NTOK, 256>>>(z, ln_a_w, ln_a_b, gA);

    // 3. qkv GEMM (2-pass weights) -> fp16 hi/lo [4096,3072]
    wconv_kernel<<<dim3(3 * DMODEL / 32, CDIM / 32), dim3(32, 8)>>>(w_attn, gBh, gBl, CDIM, 3 * DMODEL);
    mma_gemm<false, false, true, true><<<dim3(3 * DMODEL / 128, NTOK / 256), 256, SM_TOT>>>(
        gA, CDIM, gBh, gBl, b_attn, nullptr, gGh, gGl, 3 * DMODEL, CDIM);

    // 4. tensor-core attention -> y fp16 in g_A (stride 1024)
    attn_mma_kernel<<<dim3(TSEQ / 64, NHEAD, BATCH), 128, ATT_SMEM>>>(gGh, gGl, gA);

    // 5. proj GEMM (2-pass weights) -> fp32 g_h
    wconv_kernel<<<dim3(DMODEL / 32, DMODEL / 32), dim3(32, 8)>>>(w_proj, gBh, gBl, DMODEL, DMODEL);
    mma_gemm<false, true, false, true><<<dim3(DMODEL / 128, NTOK / 256), 256, SM_TOT>>>(
        gA, DMODEL, gBh, gBl, b_proj, gh, nullptr, nullptr, DMODEL, DMODEL);

    // 6. LN(concat(h, temb)) -> fp16 [4096,1088]
    ln_concat_kernel<<<NTOK, 256>>>(gh, ln_m_w, ln_m_b, gA);

    // 7. fc GEMM + GELU (single-pass weights) -> fp16 [4096,4096]
    wconv_kernel<<<dim3(4 * DMODEL / 32, CDIM / 32), dim3(32, 8)>>>(w_fc, gBh, nullptr, CDIM, 4 * DMODEL);
    mma_gemm<true, false, false, false><<<dim3(4 * DMODEL / 128, NTOK / 256), 256, SM_TOT>>>(
        gA, CDIM, gBh, nullptr, b_fc, nullptr, gGh, nullptr, 4 * DMODEL, CDIM);

    // 8. fc2 GEMM (single-pass weights) -> fp32 out
    wconv_kernel<<<dim3(DMODEL / 32, 4 * DMODEL / 32), dim3(32, 8)>>>(w_fc2, gBl, nullptr, 4 * DMODEL, DMODEL);
    mma_gemm<false, true, false, false><<<dim3(DMODEL / 128, NTOK / 256), 256, SM_TOT>>>(
        gGh, 4 * DMODEL, gBl, nullptr, b_fc2, out, nullptr, nullptr, DMODEL, 4 * DMODEL);
}

// round 17
// speedup vs baseline: 1.3783x; 1.0755x over previous
#include <cuda_runtime.h>
#include <cuda_fp16.h>
#include <cstdint>
#include <math.h>

// ---------------------------------------------------------------------------
// Problem constants
// ---------------------------------------------------------------------------
#define BATCH 2
#define TSEQ  2048
#define DMODEL 1024
#define TE    64
#define CDIM  1088
#define NHEAD 16
#define HD    64
#define NTOK  (BATCH * TSEQ)  // 4096
#define EPSLN 1e-5f

// ---------------------------------------------------------------------------
// Scratch (static device arrays; no allocation anywhere)
// ---------------------------------------------------------------------------
__device__ float g_temb[BATCH * TE];
__device__ float g_h[NTOK * DMODEL];                 // proj out fp32
__device__ __half g_A[NTOK * CDIM];                  // LN out / attn y (single fp16)
__device__ __half g_Gh[NTOK * 4 * DMODEL];           // qkv hi, later gelu (single)
__device__ __half g_Gl[NTOK * 4 * DMODEL];           // qkv lo
__device__ __half g_Bh[4096 * 1088];                 // weight hi (transposed)
__device__ __half g_Bl[4096 * 1088];                 // weight lo

__device__ __forceinline__ float gelu_exact(float x) {
    return 0.5f * x * (1.0f + erff(x * 0.70710678118654752440f));
}
__device__ __forceinline__ void split_h16(float v, __half& h, __half& l) {
    h = __float2half_rn(v);
    l = __float2half_rn(v - __half2float(h));
}
__device__ __forceinline__ uint32_t pack_h16(__half a, __half b) {
    __half2 p; p.x = a; p.y = b;
    return *(uint32_t*)&p;
}

// ---------------------------------------------------------------------------
// PTX helpers (baseline PTX only: cp.async, ldmatrix, mma.sync)
// ---------------------------------------------------------------------------
__device__ __forceinline__ uint32_t smem_u32(const void* p) {
    uint32_t a;
    asm("{ .reg .u64 t; cvta.to.shared.u64 t, %1; cvt.u32.u64 %0, t; }" : "=r"(a) : "l"(p));
    return a;
}
#define SW128(off) ((off) ^ (((off) >> 3) & 0x70))

__device__ __forceinline__ void cp16(uint32_t dst, const void* src) {
    asm volatile("cp.async.cg.shared.global [%0], [%1], 16;" :: "r"(dst), "l"(src) : "memory");
}
__device__ __forceinline__ void cp_commit() { asm volatile("cp.async.commit_group;" ::: "memory"); }
__device__ __forceinline__ void cp_wait1() { asm volatile("cp.async.wait_group 1;" ::: "memory"); }
__device__ __forceinline__ void cp_wait0() { asm volatile("cp.async.wait_group 0;" ::: "memory"); }

__device__ __forceinline__ void ldsm_x4(uint32_t (&r)[4], uint32_t addr) {
    asm volatile("ldmatrix.sync.aligned.m8n8.x4.shared.b16 {%0,%1,%2,%3}, [%4];"
        : "=r"(r[0]), "=r"(r[1]), "=r"(r[2]), "=r"(r[3]) : "r"(addr));
}
__device__ __forceinline__ void ldsm_x4_t(uint32_t (&r)[4], uint32_t addr) {
    asm volatile("ldmatrix.sync.aligned.m8n8.x4.trans.shared.b16 {%0,%1,%2,%3}, [%4];"
        : "=r"(r[0]), "=r"(r[1]), "=r"(r[2]), "=r"(r[3]) : "r"(addr));
}
__device__ __forceinline__ void mma16816(float (&d)[4], const uint32_t (&a)[4],
                                         uint32_t b0, uint32_t b1) {
    asm volatile("mma.sync.aligned.m16n8k16.row.col.f32.f16.f16.f32 "
        "{%0,%1,%2,%3}, {%4,%5,%6,%7}, {%8,%9}, {%0,%1,%2,%3};"
        : "+f"(d[0]), "+f"(d[1]), "+f"(d[2]), "+f"(d[3])
        : "r"(a[0]), "r"(a[1]), "r"(a[2]), "r"(a[3]), "r"(b0), "r"(b1));
}

// ---------------------------------------------------------------------------
// Time MLP
// ---------------------------------------------------------------------------
__global__ void time_mlp_kernel(const float* __restrict__ t,
                                const float* __restrict__ w1, const float* __restrict__ b1,
                                const float* __restrict__ w2, const float* __restrict__ b2) {
    int b = blockIdx.x;
    int e = threadIdx.x;
    __shared__ float h1[TE];
    h1[e] = gelu_exact(t[b] * w1[e] + b1[e]);
    __syncthreads();
    float acc = b2[e];
    #pragma unroll 8
    for (int i = 0; i < TE; i++) acc += h1[i] * w2[i * TE + e];
    g_temb[b * TE + e] = acc;
}

// ---------------------------------------------------------------------------
// LayerNorm over concat([x(1024), t_emb(64)]) -> single fp16 [NTOK, 1088]
// ---------------------------------------------------------------------------
__global__ void ln_concat_kernel(const float* __restrict__ x,
                                 const float* __restrict__ w,
                                 const float* __restrict__ bias,
                                 __half* __restrict__ oh) {
    const int token = blockIdx.x;
    const int b = token >> 11;
    const int tid = threadIdx.x;

    __shared__ float xs[CDIM];
    __shared__ float red[16];

    float sum = 0.f, sumsq = 0.f;
    for (int c = tid; c < CDIM; c += 256) {
        float v = (c < DMODEL) ? x[(size_t)token * DMODEL + c] : g_temb[b * TE + (c - DMODEL)];
        xs[c] = v;
        sum += v;
        sumsq += v * v;
    }
    #pragma unroll
    for (int o = 16; o > 0; o >>= 1) {
        sum   += __shfl_xor_sync(0xffffffffu, sum, o);
        sumsq += __shfl_xor_sync(0xffffffffu, sumsq, o);
    }
    int warp = tid >> 5, lane = tid & 31;
    if (lane == 0) { red[warp] = sum; red[warp + 8] = sumsq; }
    __syncthreads();
    if (tid == 0) {
        float s = 0.f, sq = 0.f;
        #pragma unroll
        for (int i = 0; i < 8; i++) { s += red[i]; sq += red[i + 8]; }
        float mu = s * (1.0f / CDIM);
        float var = sq * (1.0f / CDIM) - mu * mu;
        red[0] = mu;
        red[1] = rsqrtf(var + EPSLN);
    }
    __syncthreads();
    float mu = red[0], rs = red[1];
    for (int c = tid; c < CDIM; c += 256) {
        float v = (xs[c] - mu) * rs * w[c] + bias[c];
        oh[(size_t)token * CDIM + c] = __float2half_rn(v);
    }
}

// ---------------------------------------------------------------------------
// Weight convert + transpose: w[K,N] fp32 -> oh/ol[N,K] fp16 hi/lo
// ---------------------------------------------------------------------------
__global__ void wconv_kernel(const float* __restrict__ w,
                             __half* __restrict__ oh, __half* __restrict__ ol,
                             int K, int N) {
    __shared__ float tile[32][33];
    int nb = blockIdx.x * 32, kb = blockIdx.y * 32;
    int tx = threadIdx.x, ty = threadIdx.y;
    #pragma unroll
    for (int i = 0; i < 32; i += 8)
        tile[ty + i][tx] = w[(size_t)(kb + ty + i) * N + nb + tx];
    __syncthreads();
    #pragma unroll
    for (int i = 0; i < 32; i += 8) {
        float v = tile[tx][ty + i];
        __half h, l;
        split_h16(v, h, l);
        oh[(size_t)(nb + ty + i) * K + kb + tx] = h;
        if (ol) ol[(size_t)(nb + ty + i) * K + kb + tx] = l;
    }
}

// ---------------------------------------------------------------------------
// mma.sync fp16 GEMM: C[M,N] = A[M,K] @ B^T  (B stored [N,K]).
// TWOB=true:  B = Bh + Bl (2 passes, compensated weights) — qkv only.
// TWOB=false: B = Bh only (1 pass) — proj/fc/fc2.
// CTA 256x128, BK=64, 256 threads (8 warps 4Mx2N), warp tile m64xn64.
// ---------------------------------------------------------------------------
#define STG 65536
#define SM_TOT (2 * STG)

template <bool GELU, bool OUTF32, bool OUTHILO, bool TWOB>
__global__ __launch_bounds__(256, 1)
void mma_gemm(const __half* __restrict__ A, int lda,
              const __half* __restrict__ Bh, const __half* __restrict__ Bl,
              const float* __restrict__ bias,
              float* __restrict__ Cf, __half* __restrict__ Ch, __half* __restrict__ Cl,
              int ldc, int K) {
    extern __shared__ char smem[];
    const uint32_t sb = smem_u32(smem);
    const int tid = threadIdx.x;
    const int lane = tid & 31;
    const int wid = tid >> 5;
    const int wm = wid & 3;        // rows wm*64..+63
    const int wn = wid >> 2;       // cols wn*64..+63
    const int bm = blockIdx.y * 256;
    const int bn = blockIdx.x * 128;
    const int nch = K >> 6;

    float acc[4][8][4];
    #pragma unroll
    for (int i = 0; i < 4; i++)
        #pragma unroll
        for (int j = 0; j < 8; j++)
            #pragma unroll
            for (int q = 0; q < 4; q++) acc[i][j][q] = 0.f;

    auto load_stage = [&](int c, int s) {
        const int k0 = c * 64;
        const uint32_t base = sb + s * STG;
        #pragma unroll
        for (int i = 0; i < 8; i++) {
            int id = tid + i * 256;          // 0..2047
            int row = id >> 3;
            int c16 = id & 7;
            uint32_t off = SW128(row * 128 + c16 * 16);
            cp16(base + off, A + (size_t)(bm + row) * lda + k0 + c16 * 8);
        }
        #pragma unroll
        for (int i = 0; i < 4; i++) {
            int id = tid + i * 256;          // 0..1023
            int row = id >> 3;
            int c16 = id & 7;
            uint32_t off = SW128(row * 128 + c16 * 16);
            const size_t gb = (size_t)(bn + row) * K + k0 + c16 * 8;
            cp16(base + 32768 + off, Bh + gb);
            if (TWOB) cp16(base + 49152 + off, Bl + gb);
        }
        cp_commit();
    };

    load_stage(0, 0);

    const int a_row = (lane & 15);
    const int a_col16 = (lane >> 4) << 4;
    const int b_grp = lane >> 3;
    const int b_row = ((b_grp >> 1) << 3) + (lane & 7);
    const int b_col16 = (b_grp & 1) << 4;

    for (int c = 0; c < nch; c++) {
        const int st = c & 1;
        if (c + 1 < nch) { load_stage(c + 1, st ^ 1); cp_wait1(); }
        else             { cp_wait0(); }
        __syncthreads();

        const uint32_t a_b  = sb + st * STG;
        const uint32_t bh_b = a_b + 32768;
        const uint32_t bl_b = a_b + 49152;

        #pragma unroll
        for (int ks = 0; ks < 4; ks++) {
            const int kb = ks * 32;
            uint32_t fa[4][4];
            #pragma unroll
            for (int mt = 0; mt < 4; mt++) {
                int row = wm * 64 + mt * 16 + a_row;
                uint32_t off = SW128(row * 128 + kb + a_col16);
                ldsm_x4(fa[mt], a_b + off);
            }
            uint32_t fbh[4][4];
            #pragma unroll
            for (int nb = 0; nb < 4; nb++) {
                int row = wn * 64 + nb * 16 + b_row;
                uint32_t off = SW128(row * 128 + kb + b_col16);
                ldsm_x4(fbh[nb], bh_b + off);
            }
            #pragma unroll
            for (int mt = 0; mt < 4; mt++)
                #pragma unroll
                for (int nt = 0; nt < 8; nt++)
                    mma16816(acc[mt][nt], fa[mt],
                             fbh[nt >> 1][(nt & 1) * 2], fbh[nt >> 1][(nt & 1) * 2 + 1]);
            if (TWOB) {
                uint32_t fbl[4][4];
                #pragma unroll
                for (int nb = 0; nb < 4; nb++) {
                    int row = wn * 64 + nb * 16 + b_row;
                    uint32_t off = SW128(row * 128 + kb + b_col16);
                    ldsm_x4(fbl[nb], bl_b + off);
                }
                #pragma unroll
                for (int mt = 0; mt < 4; mt++)
                    #pragma unroll
                    for (int nt = 0; nt < 8; nt++)
                        mma16816(acc[mt][nt], fa[mt],
                                 fbl[nt >> 1][(nt & 1) * 2], fbl[nt >> 1][(nt & 1) * 2 + 1]);
            }
        }
        __syncthreads();
    }

    #pragma unroll
    for (int mt = 0; mt < 4; mt++) {
        #pragma unroll
        for (int nt = 0; nt < 8; nt++) {
            int r0  = bm + wm * 64 + mt * 16 + (lane >> 2);
            int col = bn + wn * 64 + nt * 8 + ((lane & 3) << 1);
            float bi0 = bias[col], bi1 = bias[col + 1];
            #pragma unroll
            for (int half_ = 0; half_ < 2; half_++) {
                size_t row = r0 + half_ * 8;
                float v0 = acc[mt][nt][half_ * 2 + 0] + bi0;
                float v1 = acc[mt][nt][half_ * 2 + 1] + bi1;
                if (GELU) { v0 = gelu_exact(v0); v1 = gelu_exact(v1); }
                if (OUTF32) {
                    float2 o2 = make_float2(v0, v1);
                    *(float2*)&Cf[row * ldc + col] = o2;
                } else if (OUTHILO) {
                    __half h0, l0, h1, l1;
                    split_h16(v0, h0, l0);
                    split_h16(v1, h1, l1);
                    *(uint32_t*)&Ch[row * ldc + col] = pack_h16(h0, h1);
                    *(uint32_t*)&Cl[row * ldc + col] = pack_h16(l0, l1);
                } else {
                    *(uint32_t*)&Ch[row * ldc + col] =
                        pack_h16(__float2half_rn(v0), __float2half_rn(v1));
                }
            }
        }
    }
}

// ---------------------------------------------------------------------------
// Tensor-core causal flash attention.
// QK^T: 3-pass fp16 (QhKh + QhKl + QlKh) — logits stay fully compensated.
// PV:   1-pass fp16 (P * Vh) — V rounding lands directly on y (~2.8e-4 RMS).
// grid (32, 16, 2) qt reversed; 128 threads = 4 warps, warp = m16 x n64.
// smem: Q 16KB + 2 stages x {Kh,Kl,Vh} 24KB = 64KB -> 3 CTAs/SM.
// ---------------------------------------------------------------------------
#define KVSTG 24576
#define ATT_SMEM (16384 + 2 * KVSTG)

__global__ __launch_bounds__(128, 1)
void attn_mma_kernel(const __half* __restrict__ QKVh,
                     const __half* __restrict__ QKVl,
                     __half* __restrict__ y) {
    extern __shared__ char smem[];
    const uint32_t sb = smem_u32(smem);
    const int qt = (int)gridDim.x - 1 - (int)blockIdx.x;
    const int h = blockIdx.y, b = blockIdx.z;
    const int tid = threadIdx.x, lane = tid & 31, wm = tid >> 5;
    const int base = b * TSEQ;
    const size_t qstride = 3 * DMODEL;

    const uint32_t sQh = sb, sQl = sb + 8192;

    #pragma unroll
    for (int i = 0; i < 4; i++) {
        int id = tid + i * 128;
        int row = id >> 3, c = id & 7;
        uint32_t off = SW128(row * 128 + c * 16);
        size_t g = (size_t)(base + qt * 64 + row) * qstride + h * HD + c * 8;
        cp16(sQh + off, QKVh + g);
        cp16(sQl + off, QKVl + g);
    }
    auto load_kv = [&](int kt, int s) {
        uint32_t kb_ = sb + 16384 + s * KVSTG;
        #pragma unroll
        for (int i = 0; i < 4; i++) {
            int id = tid + i * 128;
            int row = id >> 3, c = id & 7;
            uint32_t off = SW128(row * 128 + c * 16);
            size_t gk = (size_t)(base + kt * 64 + row) * qstride + DMODEL + h * HD + c * 8;
            size_t gv = gk + DMODEL;
            cp16(kb_ + off,          QKVh + gk);
            cp16(kb_ + 8192 + off,   QKVl + gk);
            cp16(kb_ + 16384 + off,  QKVh + gv);
        }
    };
    load_kv(0, 0);
    cp_commit();

    float oacc[8][4];
    #pragma unroll
    for (int i = 0; i < 8; i++)
        #pragma unroll
        for (int j = 0; j < 4; j++) oacc[i][j] = 0.f;
    float m0 = -INFINITY, m1 = -INFINITY, l0 = 0.f, l1 = 0.f;

    for (int kt = 0; kt <= qt; kt++) {
        const int st = kt & 1;
        if (kt < qt) { load_kv(kt + 1, st ^ 1); cp_commit(); cp_wait1(); }
        else         { cp_wait0(); }
        __syncthreads();

        const uint32_t sKh = sb + 16384 + st * KVSTG;
        const uint32_t sKl = sKh + 8192;
        const uint32_t sVh = sKh + 16384;

        float sacc[8][4];
        #pragma unroll
        for (int i = 0; i < 8; i++)
            #pragma unroll
            for (int j = 0; j < 4; j++) sacc[i][j] = 0.f;

        #pragma unroll
        for (int ks = 0; ks < 4; ks++) {
            uint32_t qh[4], ql[4];
            {
                int r = wm * 16 + (lane & 15);
                int byt = ks * 32 + ((lane >> 4) << 4);
                uint32_t off = SW128(r * 128 + byt);
                ldsm_x4(qh, sQh + off);
                ldsm_x4(ql, sQl + off);
            }
            #pragma unroll
            for (int nb2 = 0; nb2 < 4; nb2++) {
                uint32_t kh[4], kl[4];
                int grp = lane >> 3;
                int r = nb2 * 16 + ((grp >> 1) << 3) + (lane & 7);
                int byt = ks * 32 + ((grp & 1) << 4);
                uint32_t off = SW128(r * 128 + byt);
                ldsm_x4(kh, sKh + off);
                ldsm_x4(kl, sKl + off);
                mma16816(sacc[2 * nb2],     qh, kh[0], kh[1]);
                mma16816(sacc[2 * nb2],     qh, kl[0], kl[1]);
                mma16816(sacc[2 * nb2],     ql, kh[0], kh[1]);
                mma16816(sacc[2 * nb2 + 1], qh, kh[2], kh[3]);
                mma16816(sacc[2 * nb2 + 1], qh, kl[2], kl[3]);
                mma16816(sacc[2 * nb2 + 1], ql, kh[2], kh[3]);
            }
        }

        const bool diag = (kt == qt);
        const int lr0 = wm * 16 + (lane >> 2);
        #pragma unroll
        for (int nt = 0; nt < 8; nt++) {
            int c0 = nt * 8 + 2 * (lane & 3);
            #pragma unroll
            for (int j = 0; j < 4; j++) {
                float v = sacc[nt][j] * 0.125f;
                if (diag && (c0 + (j & 1)) > (lr0 + (j >> 1) * 8)) v = -1e30f;
                sacc[nt][j] = v;
            }
        }

        float r0m = -1e30f, r1m = -1e30f;
        #pragma unroll
        for (int nt = 0; nt < 8; nt++) {
            r0m = fmaxf(r0m, fmaxf(sacc[nt][0], sacc[nt][1]));
            r1m = fmaxf(r1m, fmaxf(sacc[nt][2], sacc[nt][3]));
        }
        r0m = fmaxf(r0m, __shfl_xor_sync(0xffffffffu, r0m, 1));
        r0m = fmaxf(r0m, __shfl_xor_sync(0xffffffffu, r0m, 2));
        r1m = fmaxf(r1m, __shfl_xor_sync(0xffffffffu, r1m, 1));
        r1m = fmaxf(r1m, __shfl_xor_sync(0xffffffffu, r1m, 2));
        float m0n = fmaxf(m0, r0m), m1n = fmaxf(m1, r1m);
        float cr0 = __expf(m0 - m0n), cr1 = __expf(m1 - m1n);
        m0 = m0n; m1 = m1n;
        l0 *= cr0; l1 *= cr1;
        #pragma unroll
        for (int nt = 0; nt < 8; nt++) {
            oacc[nt][0] *= cr0; oacc[nt][1] *= cr0;
            oacc[nt][2] *= cr1; oacc[nt][3] *= cr1;
        }
        float ps0 = 0.f, ps1 = 0.f;
        #pragma unroll
        for (int nt = 0; nt < 8; nt++) {
            float p0 = __expf(sacc[nt][0] - m0);
            float p1 = __expf(sacc[nt][1] - m0);
            float p2 = __expf(sacc[nt][2] - m1);
            float p3 = __expf(sacc[nt][3] - m1);
            ps0 += p0 + p1; ps1 += p2 + p3;
            sacc[nt][0] = p0; sacc[nt][1] = p1; sacc[nt][2] = p2; sacc[nt][3] = p3;
        }
        l0 += ps0; l1 += ps1;

        // --- O += P * Vh (single pass) ---
        #pragma unroll
        for (int s = 0; s < 4; s++) {
            uint32_t aP[4];
            #pragma unroll
            for (int half_ = 0; half_ < 2; half_++) {
                int blk = 2 * s + half_;
                aP[2 * half_ + 0] = pack_h16(__float2half_rn(sacc[blk][0]),
                                             __float2half_rn(sacc[blk][1]));
                aP[2 * half_ + 1] = pack_h16(__float2half_rn(sacc[blk][2]),
                                             __float2half_rn(sacc[blk][3]));
            }
            #pragma unroll
            for (int dd = 0; dd < 4; dd++) {
                uint32_t vh[4];
                int grp = lane >> 3;
                int key = s * 16 + (grp & 1) * 8 + (lane & 7);
                int byt = dd * 32 + ((grp >> 1) << 4);
                uint32_t off = SW128(key * 128 + byt);
                ldsm_x4_t(vh, sVh + off);
                mma16816(oacc[2 * dd],     aP, vh[0], vh[1]);
                mma16816(oacc[2 * dd + 1], aP, vh[2], vh[3]);
            }
        }
        __syncthreads();
    }

    l0 += __shfl_xor_sync(0xffffffffu, l0, 1);
    l0 += __shfl_xor_sync(0xffffffffu, l0, 2);
    l1 += __shfl_xor_sync(0xffffffffu, l1, 1);
    l1 += __shfl_xor_sync(0xffffffffu, l1, 2);
    float inv0 = 1.0f / l0, inv1 = 1.0f / l1;

    const size_t gr0 = (size_t)(base + qt * 64 + wm * 16 + (lane >> 2));
    const int colb = h * HD + 2 * (lane & 3);
    #pragma unroll
    for (int nt = 0; nt < 8; nt++) {
        int col = colb + nt * 8;
        *(uint32_t*)&y[gr0 * DMODEL + col] =
            pack_h16(__float2half_rn(oacc[nt][0] * inv0),
                     __float2half_rn(oacc[nt][1] * inv0));
        *(uint32_t*)&y[(gr0 + 8) * DMODEL + col] =
            pack_h16(__float2half_rn(oacc[nt][2] * inv1),
                     __float2half_rn(oacc[nt][3] * inv1));
    }
}

// ---------------------------------------------------------------------------
// Launch
// ---------------------------------------------------------------------------
extern "C" void kernel_launch(void* const* d_in, const int* in_sizes, int n_in,
                              void* d_out, int out_size) {
    const float* z      = (const float*)d_in[0];
    const float* t      = (const float*)d_in[1];
    const float* w_t1   = (const float*)d_in[2];
    const float* b_t1   = (const float*)d_in[3];
    const float* w_t2   = (const float*)d_in[4];
    const float* b_t2   = (const float*)d_in[5];
    const float* ln_a_w = (const float*)d_in[6];
    const float* ln_a_b = (const float*)d_in[7];
    const float* w_attn = (const float*)d_in[8];
    const float* b_attn = (const float*)d_in[9];
    const float* w_proj = (const float*)d_in[10];
    const float* b_proj = (const float*)d_in[11];
    const float* ln_m_w = (const float*)d_in[12];
    const float* ln_m_b = (const float*)d_in[13];
    const float* w_fc   = (const float*)d_in[14];
    const float* b_fc   = (const float*)d_in[15];
    const float* w_fc2  = (const float*)d_in[16];
    const float* b_fc2  = (const float*)d_in[17];
    float* out = (float*)d_out;
    (void)n_in; (void)in_sizes; (void)out_size;

    float* gh;
    __half *gA, *gGh, *gGl, *gBh, *gBl;
    cudaGetSymbolAddress((void**)&gh,  g_h);
    cudaGetSymbolAddress((void**)&gA,  g_A);
    cudaGetSymbolAddress((void**)&gGh, g_Gh);
    cudaGetSymbolAddress((void**)&gGl, g_Gl);
    cudaGetSymbolAddress((void**)&gBh, g_Bh);
    cudaGetSymbolAddress((void**)&gBl, g_Bl);

    cudaFuncSetAttribute(mma_gemm<false, false, true, true>,
                         cudaFuncAttributeMaxDynamicSharedMemorySize, SM_TOT);
    cudaFuncSetAttribute(mma_gemm<true, false, false, false>,
                         cudaFuncAttributeMaxDynamicSharedMemorySize, SM_TOT);
    cudaFuncSetAttribute(mma_gemm<false, true, false, false>,
                         cudaFuncAttributeMaxDynamicSharedMemorySize, SM_TOT);
    cudaFuncSetAttribute(attn_mma_kernel,
                         cudaFuncAttributeMaxDynamicSharedMemorySize, ATT_SMEM);

    // 1. time embedding
    time_mlp_kernel<<<BATCH, TE>>>(t, w_t1, b_t1, w_t2, b_t2);

    // 2. LN(concat(z, temb)) -> fp16 [4096,1088]
    ln_concat_kernel<<<NTOK, 256>>>(z, ln_a_w, ln_a_b, gA);

    // 3. qkv GEMM (2-pass weights) -> fp16 hi/lo [4096,3072]
    wconv_kernel<<<dim3(3 * DMODEL / 32, CDIM / 32), dim3(32, 8)>>>(w_attn, gBh, gBl, CDIM, 3 * DMODEL);
    mma_gemm<false, false, true, true><<<dim3(3 * DMODEL / 128, NTOK / 256), 256, SM_TOT>>>(
        gA, CDIM, gBh, gBl, b_attn, nullptr, gGh, gGl, 3 * DMODEL, CDIM);

    // 4. tensor-core attention (QK 3-pass, PV 1-pass) -> y fp16 in g_A
    attn_mma_kernel<<<dim3(TSEQ / 64, NHEAD, BATCH), 128, ATT_SMEM>>>(gGh, gGl, gA);

    // 5. proj GEMM (single-pass weights) -> fp32 g_h
    wconv_kernel<<<dim3(DMODEL / 32, DMODEL / 32), dim3(32, 8)>>>(w_proj, gBh, nullptr, DMODEL, DMODEL);
    mma_gemm<false, true, false, false><<<dim3(DMODEL / 128, NTOK / 256), 256, SM_TOT>>>(
        gA, DMODEL, gBh, nullptr, b_proj, gh, nullptr, nullptr, DMODEL, DMODEL);

    // 6. LN(concat(h, temb)) -> fp16 [4096,1088]
    ln_concat_kernel<<<NTOK, 256>>>(gh, ln_m_w, ln_m_b, gA);

    // 7. fc GEMM + GELU (single-pass weights) -> fp16 [4096,4096]
    wconv_kernel<<<dim3(4 * DMODEL / 32, CDIM / 32), dim3(32, 8)>>>(w_fc, gBh, nullptr, CDIM, 4 * DMODEL);
    mma_gemm<true, false, false, false><<<dim3(4 * DMODEL / 128, NTOK / 256), 256, SM_TOT>>>(
        gA, CDIM, gBh, nullptr, b_fc, nullptr, gGh, nullptr, 4 * DMODEL, CDIM);

    // 8. fc2 GEMM (single-pass weights) -> fp32 out
    wconv_kernel<<<dim3(DMODEL / 32, 4 * DMODEL / 32), dim3(32, 8)>>>(w_fc2, gBl, nullptr, 4 * DMODEL, DMODEL);
    mma_gemm<false, true, false, false><<<dim3(DMODEL / 128, NTOK / 256), 256, SM_TOT>>>(
        gGh, 4 * DMODEL, gBl, nullptr, b_fc2, out, nullptr, nullptr, DMODEL, 4 * DMODEL);
}